// round 2
// baseline (speedup 1.0000x reference)
#include <cuda_runtime.h>
#include <math.h>

#define NNODES 200000
#define NEDGES 3200000

// ---------------- scratch (no allocations allowed) ----------------
__device__ __align__(256) float d_deg[NNODES];
__device__ __align__(256) float d_dinv[NNODES];
__device__ __align__(256) int   d_src[NEDGES];
__device__ __align__(256) int   d_dst[NEDGES];
__device__ __align__(256) float d_g1[(size_t)NNODES * 128];
__device__ __align__(256) float d_o1[(size_t)NNODES * 128];
__device__ __align__(256) float d_g2[(size_t)NNODES * 64];
__device__ __align__(256) float d_o2[(size_t)NNODES * 64];
__device__ __align__(256) float d_g3[(size_t)NNODES * 8];
__device__ __align__(256) float d_o3[(size_t)NNODES * 8];
__device__ int d_is64;

// ---------------- helpers ----------------
__device__ __forceinline__ void red_add_f4(float* p, float4 v) {
    asm volatile("red.global.add.v4.f32 [%0], {%1, %2, %3, %4};"
                 :: "l"(p), "f"(v.x), "f"(v.y), "f"(v.z), "f"(v.w)
                 : "memory");
}

// ---------------- edge dtype detection ----------------
// int64 layout (little endian, values < 2^31): odd int32 words are zero.
// int32 layout: words are uniform random node ids, ~never 64 zeros in a row.
__global__ void k_detect(const int* __restrict__ ei32) {
    if (threadIdx.x == 0 && blockIdx.x == 0) {
        int zeros = 0;
#pragma unroll
        for (int i = 0; i < 64; i++)
            if (ei32[2 * i + 1] == 0) zeros++;
        d_is64 = (zeros >= 60) ? 1 : 0;
    }
}

// ---------------- degree / dinv ----------------
__global__ void k_deg_init() {
    int i = blockIdx.x * blockDim.x + threadIdx.x;
    if (i < NNODES) d_deg[i] = 1.0f;   // self-loop
}

__global__ void k_edge_prep(const void* __restrict__ ei) {
    int e = blockIdx.x * blockDim.x + threadIdx.x;
    if (e >= NEDGES) return;
    int s, d;
    if (d_is64) {
        const long long* p = (const long long*)ei;
        s = (int)p[e];
        d = (int)p[(size_t)NEDGES + e];
    } else {
        const int* p = (const int*)ei;
        s = p[e];
        d = p[NEDGES + e];
    }
    d_src[e] = s;
    d_dst[e] = d;
    atomicAdd(&d_deg[d], 1.0f);
}

__global__ void k_dinv() {
    int i = blockIdx.x * blockDim.x + threadIdx.x;
    if (i < NNODES) d_dinv[i] = rsqrtf(d_deg[i]);
}

// ---------------- tiled SIMT GEMM with fused dinv scale ----------------
// C = dinv[row] * (A[N,K] @ W[K(+2),BN])   (optional rank-2 extra rows of W)
// writes result to BOTH g (gather source) and o (aggregation init = self-loop)
template<int K, int BN, bool EXTRA>
__global__ void __launch_bounds__(256)
k_gemm(const float* __restrict__ A,
       const float* __restrict__ W,
       const float* __restrict__ hist,
       const float* __restrict__ subg,
       float* __restrict__ g,
       float* __restrict__ o)
{
    constexpr int BM = 64;
    constexpr int BK = 16;
    constexpr int TN = 4;
    constexpr int TM = (BM * BN) / (256 * TN);   // 8 for BN=128, 4 for BN=64
    constexpr int NT = BN / TN;                  // threads along n

    __shared__ float As[BK][BM + 4];
    __shared__ float Bs[BK][BN];

    const int tid = threadIdx.x;
    const int tn0 = (tid % NT) * TN;
    const int tm0 = (tid / NT) * TM;
    const int rowBase = blockIdx.x * BM;

    float acc[TM][TN];
#pragma unroll
    for (int i = 0; i < TM; i++)
#pragma unroll
        for (int j = 0; j < TN; j++) acc[i][j] = 0.f;

    // A-tile load mapping: one float4 per thread per k-step
    const int am  = tid / (BK / 4);         // 0..63
    const int ak4 = (tid % (BK / 4)) * 4;   // 0,4,8,12
    const float* Arow = A + (size_t)(rowBase + am) * K;

    for (int k0 = 0; k0 < K; k0 += BK) {
        float4 av = *(const float4*)(Arow + k0 + ak4);
        As[ak4 + 0][am] = av.x;
        As[ak4 + 1][am] = av.y;
        As[ak4 + 2][am] = av.z;
        As[ak4 + 3][am] = av.w;
#pragma unroll
        for (int i = tid * 4; i < BK * BN; i += 256 * 4) {
            int r = i / BN, c = i % BN;
            *(float4*)&Bs[r][c] = *(const float4*)(W + (size_t)(k0 + r) * BN + c);
        }
        __syncthreads();
#pragma unroll
        for (int kk = 0; kk < BK; kk++) {
            float a[TM], b[TN];
#pragma unroll
            for (int i = 0; i < TM; i++) a[i] = As[kk][tm0 + i];
#pragma unroll
            for (int j = 0; j < TN; j++) b[j] = Bs[kk][tn0 + j];
#pragma unroll
            for (int i = 0; i < TM; i++)
#pragma unroll
                for (int j = 0; j < TN; j++)
                    acc[i][j] = fmaf(a[i], b[j], acc[i][j]);
        }
        __syncthreads();
    }

#pragma unroll
    for (int i = 0; i < TM; i++) {
        int row = rowBase + tm0 + i;
        float dv = d_dinv[row];
        float hv = 0.f, sv = 0.f;
        if (EXTRA) { hv = hist[row]; sv = subg[row]; }
        float4 out4;
        float vals[TN];
#pragma unroll
        for (int j = 0; j < TN; j++) {
            float x = acc[i][j];
            if (EXTRA) {
                x = fmaf(hv, __ldg(&W[(size_t)K * BN + tn0 + j]), x);
                x = fmaf(sv, __ldg(&W[(size_t)(K + 1) * BN + tn0 + j]), x);
            }
            vals[j] = x * dv;
        }
        out4.x = vals[0]; out4.y = vals[1]; out4.z = vals[2]; out4.w = vals[3];
        *(float4*)(g + (size_t)row * BN + tn0) = out4;
        *(float4*)(o + (size_t)row * BN + tn0) = out4;
    }
}

// ---------------- edge scatter: o[dst] += g[src], vector red ----------------
template<int F>
__global__ void k_scatter(const float* __restrict__ g, float* __restrict__ o) {
    constexpr int C = F / 4;                 // float4 chunks per edge
    int idx = blockIdx.x * blockDim.x + threadIdx.x;
    if (idx >= NEDGES * C) return;
    int e = idx / C;
    int c = idx % C;
    int s = __ldg(&d_src[e]);
    int d = __ldg(&d_dst[e]);
    float4 v = *(const float4*)(g + (size_t)s * F + c * 4);
    red_add_f4(o + (size_t)d * F + c * 4, v);
}

// ---------------- finalize: h = relu(dinv*agg + b), in place ----------------
template<int F>
__global__ void k_finalize(float* __restrict__ o, const float* __restrict__ b) {
    int idx = blockIdx.x * blockDim.x + threadIdx.x;
    if (idx < NNODES * F) {
        int n = idx / F;
        int c = idx % F;
        o[idx] = fmaxf(fmaf(d_dinv[n], o[idx], __ldg(&b[c])), 0.f);
    }
}

// ---------------- layer 3 GEMM: [N,64] -> [N,8], fused dinv ----------------
__global__ void __launch_bounds__(256) k_gemm3(const float* __restrict__ W3) {
    __shared__ float Ws[64 * 8];
    __shared__ float Hs[32][65];
    int tid = threadIdx.x;
    for (int i = tid; i < 512; i += 256) Ws[i] = W3[i];
    int nodeBase = blockIdx.x * 32;
    for (int i = tid; i < 512; i += 256) {
        int r = i / 16, c4 = i % 16;
        float4 v = *(const float4*)(d_o2 + (size_t)(nodeBase + r) * 64 + c4 * 4);
        Hs[r][c4 * 4 + 0] = v.x; Hs[r][c4 * 4 + 1] = v.y;
        Hs[r][c4 * 4 + 2] = v.z; Hs[r][c4 * 4 + 3] = v.w;
    }
    __syncthreads();
    int ln = tid / 8, col = tid % 8;
    float acc = 0.f;
#pragma unroll
    for (int k = 0; k < 64; k++) acc = fmaf(Hs[ln][k], Ws[k * 8 + col], acc);
    int node = nodeBase + ln;
    float v = d_dinv[node] * acc;
    d_g3[(size_t)node * 8 + col] = v;
    d_o3[(size_t)node * 8 + col] = v;
}

// ---------------- final head: relu(dinv*o3+b3) @ Wc + bc ----------------
__global__ void k_head(const float* __restrict__ Wc, const float* __restrict__ bc,
                       const float* __restrict__ b3, float* __restrict__ out) {
    int n = blockIdx.x * blockDim.x + threadIdx.x;
    if (n >= NNODES) return;
    float dv = d_dinv[n];
    float4 p0 = *(const float4*)(d_o3 + (size_t)n * 8);
    float4 p1 = *(const float4*)(d_o3 + (size_t)n * 8 + 4);
    float h[8] = {p0.x, p0.y, p0.z, p0.w, p1.x, p1.y, p1.z, p1.w};
    float r0 = __ldg(&bc[0]), r1 = __ldg(&bc[1]), r2 = __ldg(&bc[2]);
#pragma unroll
    for (int j = 0; j < 8; j++) {
        float hv = fmaxf(fmaf(dv, h[j], __ldg(&b3[j])), 0.f);
        r0 = fmaf(hv, __ldg(&Wc[j * 3 + 0]), r0);
        r1 = fmaf(hv, __ldg(&Wc[j * 3 + 1]), r1);
        r2 = fmaf(hv, __ldg(&Wc[j * 3 + 2]), r2);
    }
    out[(size_t)n * 3 + 0] = r0;
    out[(size_t)n * 3 + 1] = r1;
    out[(size_t)n * 3 + 2] = r2;
}

// ---------------- launch ----------------
extern "C" void kernel_launch(void* const* d_in, const int* in_sizes, int n_in,
                              void* d_out, int out_size) {
    const float* latent = (const float*)d_in[0];
    const float* hist   = (const float*)d_in[1];
    const float* subg   = (const float*)d_in[2];
    const void*  ei     = d_in[3];
    const float* W1 = (const float*)d_in[4];
    const float* b1 = (const float*)d_in[5];
    const float* W2 = (const float*)d_in[6];
    const float* b2 = (const float*)d_in[7];
    const float* W3 = (const float*)d_in[8];
    const float* b3 = (const float*)d_in[9];
    const float* Wc = (const float*)d_in[10];
    const float* bc = (const float*)d_in[11];
    float* out = (float*)d_out;

    float *g1, *o1, *g2, *o2, *g3, *o3;
    cudaGetSymbolAddress((void**)&g1, d_g1);
    cudaGetSymbolAddress((void**)&o1, d_o1);
    cudaGetSymbolAddress((void**)&g2, d_g2);
    cudaGetSymbolAddress((void**)&o2, d_o2);
    cudaGetSymbolAddress((void**)&g3, d_g3);
    cudaGetSymbolAddress((void**)&o3, d_o3);

    k_detect<<<1, 32>>>((const int*)ei);
    k_deg_init<<<(NNODES + 255) / 256, 256>>>();
    k_edge_prep<<<(NEDGES + 255) / 256, 256>>>(ei);
    k_dinv<<<(NNODES + 255) / 256, 256>>>();

    // layer 1: K=256 (+2 extra rows), Fout=128
    k_gemm<256, 128, true><<<NNODES / 64, 256>>>(latent, W1, hist, subg, g1, o1);
    k_scatter<128><<<(NEDGES * 32 + 255) / 256, 256>>>(g1, o1);
    k_finalize<128><<<(NNODES * 128 + 255) / 256, 256>>>(o1, b1);

    // layer 2: K=128, Fout=64
    k_gemm<128, 64, false><<<NNODES / 64, 256>>>(o1, W2, nullptr, nullptr, g2, o2);
    k_scatter<64><<<(NEDGES * 16 + 255) / 256, 256>>>(g2, o2);
    k_finalize<64><<<(NNODES * 64 + 255) / 256, 256>>>(o2, b2);

    // layer 3: K=64, Fout=8
    k_gemm3<<<NNODES / 32, 256>>>(W3);
    k_scatter<8><<<(NEDGES * 2 + 255) / 256, 256>>>(g3, o3);

    // head (fuses relu-finalize of layer 3)
    k_head<<<(NNODES + 255) / 256, 256>>>(Wc, bc, b3, out);
}

// round 3
// speedup vs baseline: 1.0376x; 1.0376x over previous
#include <cuda_runtime.h>
#include <math.h>

#define NNODES 200000
#define NEDGES 3200000

// ---------------- scratch (no allocations allowed) ----------------
__device__ __align__(256) float d_deg[NNODES];
__device__ __align__(256) float d_dinv[NNODES];
__device__ __align__(256) int   d_src[NEDGES];
__device__ __align__(256) int   d_dst[NEDGES];
__device__ __align__(256) float d_g1[(size_t)NNODES * 128];
__device__ __align__(256) float d_o1[(size_t)NNODES * 128];
__device__ __align__(256) float d_g2[(size_t)NNODES * 64];
__device__ __align__(256) float d_o2[(size_t)NNODES * 64];
__device__ __align__(256) float d_g3[(size_t)NNODES * 8];
__device__ __align__(256) float d_o3[(size_t)NNODES * 8];
__device__ int d_is64;

// ---------------- helpers ----------------
__device__ __forceinline__ void red_add_f4(float* p, float4 v) {
    asm volatile("red.global.add.v4.f32 [%0], {%1, %2, %3, %4};"
                 :: "l"(p), "f"(v.x), "f"(v.y), "f"(v.z), "f"(v.w)
                 : "memory");
}

// ---------------- edge dtype detection ----------------
__global__ void k_detect(const int* __restrict__ ei32) {
    if (threadIdx.x == 0 && blockIdx.x == 0) {
        int zeros = 0;
#pragma unroll
        for (int i = 0; i < 64; i++)
            if (ei32[2 * i + 1] == 0) zeros++;
        d_is64 = (zeros >= 60) ? 1 : 0;
    }
}

// ---------------- degree / dinv ----------------
__global__ void k_deg_init() {
    int i = blockIdx.x * blockDim.x + threadIdx.x;
    if (i < NNODES) d_deg[i] = 1.0f;   // self-loop
}

__global__ void k_edge_prep(const void* __restrict__ ei) {
    int e = blockIdx.x * blockDim.x + threadIdx.x;
    if (e >= NEDGES) return;
    int s, d;
    if (d_is64) {
        const long long* p = (const long long*)ei;
        s = (int)p[e];
        d = (int)p[(size_t)NEDGES + e];
    } else {
        const int* p = (const int*)ei;
        s = p[e];
        d = p[NEDGES + e];
    }
    d_src[e] = s;
    d_dst[e] = d;
    atomicAdd(&d_deg[d], 1.0f);
}

__global__ void k_dinv() {
    int i = blockIdx.x * blockDim.x + threadIdx.x;
    if (i < NNODES) d_dinv[i] = rsqrtf(d_deg[i]);
}

// ---------------- tiled SIMT GEMM, 8x8 microtile, reg-prefetch -------------
// C = dinv[row] * (Ain[N,K] @ W[K(+2),BN])
//   FUSE_IN: A element = relu(dinv[row]*raw + bin[k])  (fuses prev finalize)
//   EXTRA:   rank-2 correction from hist/subg against W rows K, K+1
// writes result to BOTH g (gather source) and o (self-loop init for scatter)
template<int K, int BN, int THREADS, bool EXTRA, bool FUSE_IN>
__global__ void __launch_bounds__(THREADS)
k_gemm(const float* __restrict__ A,
       const float* __restrict__ W,
       const float* __restrict__ hist,
       const float* __restrict__ subg,
       const float* __restrict__ bin,
       float* __restrict__ g,
       float* __restrict__ o)
{
    constexpr int BM = 128;
    constexpr int BK = 16;
    constexpr int TM = 8;
    constexpr int TN = 8;
    constexpr int NT = BN / TN;                  // threads along n
    static_assert(NT * (BM / TM) == THREADS, "thread shape");
    constexpr int LA = (BM * BK / 4) / THREADS;  // float4 A loads / thread
    constexpr int LB = (BK * BN / 4) / THREADS;  // float4 B loads / thread

    __shared__ float As[BK][BM + 4];
    __shared__ float Bs[BK][BN];

    const int tid = threadIdx.x;
    const int tn0 = (tid % NT) * TN;
    const int tm0 = (tid / NT) * TM;
    const int rowBase = blockIdx.x * BM;

    float acc[TM][TN];
#pragma unroll
    for (int i = 0; i < TM; i++)
#pragma unroll
        for (int j = 0; j < TN; j++) acc[i][j] = 0.f;

    // A load mapping: idx -> (row in tile, k-quad)
    int arow[LA], ak4[LA];
#pragma unroll
    for (int u = 0; u < LA; u++) {
        int idx = tid + u * THREADS;
        arow[u] = idx / (BK / 4);
        ak4[u]  = (idx % (BK / 4)) * 4;
    }
    float4 ra[LA], rb[LB];

    auto loadA = [&](int k0) {
#pragma unroll
        for (int u = 0; u < LA; u++) {
            int row = rowBase + arow[u];
            float4 v = make_float4(0.f, 0.f, 0.f, 0.f);
            if (row < NNODES) {
                v = *(const float4*)(A + (size_t)row * K + k0 + ak4[u]);
                if (FUSE_IN) {
                    float dv = d_dinv[row];
                    int kk = k0 + ak4[u];
                    v.x = fmaxf(fmaf(dv, v.x, __ldg(&bin[kk + 0])), 0.f);
                    v.y = fmaxf(fmaf(dv, v.y, __ldg(&bin[kk + 1])), 0.f);
                    v.z = fmaxf(fmaf(dv, v.z, __ldg(&bin[kk + 2])), 0.f);
                    v.w = fmaxf(fmaf(dv, v.w, __ldg(&bin[kk + 3])), 0.f);
                }
            }
            ra[u] = v;
        }
    };
    auto loadB = [&](int k0) {
#pragma unroll
        for (int u = 0; u < LB; u++) {
            int idx = tid + u * THREADS;
            int r = idx / (BN / 4), c4 = (idx % (BN / 4)) * 4;
            rb[u] = *(const float4*)(W + (size_t)(k0 + r) * BN + c4);
        }
    };
    auto stage = [&]() {
#pragma unroll
        for (int u = 0; u < LA; u++) {
            As[ak4[u] + 0][arow[u]] = ra[u].x;
            As[ak4[u] + 1][arow[u]] = ra[u].y;
            As[ak4[u] + 2][arow[u]] = ra[u].z;
            As[ak4[u] + 3][arow[u]] = ra[u].w;
        }
#pragma unroll
        for (int u = 0; u < LB; u++) {
            int idx = tid + u * THREADS;
            int r = idx / (BN / 4), c4 = (idx % (BN / 4)) * 4;
            *(float4*)&Bs[r][c4] = rb[u];
        }
    };

    loadA(0); loadB(0);

    for (int k0 = 0; k0 < K; k0 += BK) {
        stage();
        __syncthreads();
        if (k0 + BK < K) { loadA(k0 + BK); loadB(k0 + BK); }
#pragma unroll
        for (int kk = 0; kk < BK; kk++) {
            float4 a0 = *(const float4*)&As[kk][tm0];
            float4 a1 = *(const float4*)&As[kk][tm0 + 4];
            float4 b0 = *(const float4*)&Bs[kk][tn0];
            float4 b1 = *(const float4*)&Bs[kk][tn0 + 4];
            float av[TM] = {a0.x, a0.y, a0.z, a0.w, a1.x, a1.y, a1.z, a1.w};
            float bv[TN] = {b0.x, b0.y, b0.z, b0.w, b1.x, b1.y, b1.z, b1.w};
#pragma unroll
            for (int i = 0; i < TM; i++)
#pragma unroll
                for (int j = 0; j < TN; j++)
                    acc[i][j] = fmaf(av[i], bv[j], acc[i][j]);
        }
        __syncthreads();
    }

#pragma unroll
    for (int i = 0; i < TM; i++) {
        int row = rowBase + tm0 + i;
        if (row >= NNODES) break;
        float dv = d_dinv[row];
        float hv = 0.f, sv = 0.f;
        if (EXTRA) { hv = hist[row]; sv = subg[row]; }
#pragma unroll
        for (int j4 = 0; j4 < TN; j4 += 4) {
            float4 out4;
            float vals[4];
#pragma unroll
            for (int j = 0; j < 4; j++) {
                float x = acc[i][j4 + j];
                if (EXTRA) {
                    x = fmaf(hv, __ldg(&W[(size_t)K * BN + tn0 + j4 + j]), x);
                    x = fmaf(sv, __ldg(&W[(size_t)(K + 1) * BN + tn0 + j4 + j]), x);
                }
                vals[j] = x * dv;
            }
            out4.x = vals[0]; out4.y = vals[1]; out4.z = vals[2]; out4.w = vals[3];
            *(float4*)(g + (size_t)row * BN + tn0 + j4) = out4;
            *(float4*)(o + (size_t)row * BN + tn0 + j4) = out4;
        }
    }
}

// ---------------- edge scatter: o[dst] += g[src], vector red ----------------
template<int F>
__global__ void k_scatter(const float* __restrict__ g, float* __restrict__ o) {
    constexpr int C = F / 4;                 // float4 chunks per edge
    long long idx = (long long)blockIdx.x * blockDim.x + threadIdx.x;
    if (idx >= (long long)NEDGES * C) return;
    int e = (int)(idx / C);
    int c = (int)(idx % C);
    int s = __ldg(&d_src[e]);
    int d = __ldg(&d_dst[e]);
    float4 v = *(const float4*)(g + (size_t)s * F + c * 4);
    red_add_f4(o + (size_t)d * F + c * 4, v);
}

// ------- layer 3 GEMM: [N,64] -> [N,8], fused input relu + dinv scale ------
__global__ void __launch_bounds__(256) k_gemm3(const float* __restrict__ W3,
                                               const float* __restrict__ b2) {
    __shared__ float Ws[64 * 8];
    __shared__ float Bb[64];
    __shared__ float Hs[32][65];
    int tid = threadIdx.x;
    for (int i = tid; i < 512; i += 256) Ws[i] = W3[i];
    if (tid < 64) Bb[tid] = b2[tid];
    int nodeBase = blockIdx.x * 32;
    __syncthreads();
    for (int i = tid; i < 512; i += 256) {
        int r = i / 16, c4 = i % 16;
        int node = nodeBase + r;
        float dv = d_dinv[node];
        float4 v = *(const float4*)(d_o2 + (size_t)node * 64 + c4 * 4);
        Hs[r][c4 * 4 + 0] = fmaxf(fmaf(dv, v.x, Bb[c4 * 4 + 0]), 0.f);
        Hs[r][c4 * 4 + 1] = fmaxf(fmaf(dv, v.y, Bb[c4 * 4 + 1]), 0.f);
        Hs[r][c4 * 4 + 2] = fmaxf(fmaf(dv, v.z, Bb[c4 * 4 + 2]), 0.f);
        Hs[r][c4 * 4 + 3] = fmaxf(fmaf(dv, v.w, Bb[c4 * 4 + 3]), 0.f);
    }
    __syncthreads();
    int ln = tid / 8, col = tid % 8;
    float acc = 0.f;
#pragma unroll
    for (int k = 0; k < 64; k++) acc = fmaf(Hs[ln][k], Ws[k * 8 + col], acc);
    int node = nodeBase + ln;
    float v = d_dinv[node] * acc;
    d_g3[(size_t)node * 8 + col] = v;
    d_o3[(size_t)node * 8 + col] = v;
}

// ---------------- final head: relu(dinv*o3+b3) @ Wc + bc ----------------
__global__ void k_head(const float* __restrict__ Wc, const float* __restrict__ bc,
                       const float* __restrict__ b3, float* __restrict__ out) {
    int n = blockIdx.x * blockDim.x + threadIdx.x;
    if (n >= NNODES) return;
    float dv = d_dinv[n];
    float4 p0 = *(const float4*)(d_o3 + (size_t)n * 8);
    float4 p1 = *(const float4*)(d_o3 + (size_t)n * 8 + 4);
    float h[8] = {p0.x, p0.y, p0.z, p0.w, p1.x, p1.y, p1.z, p1.w};
    float r0 = __ldg(&bc[0]), r1 = __ldg(&bc[1]), r2 = __ldg(&bc[2]);
#pragma unroll
    for (int j = 0; j < 8; j++) {
        float hv = fmaxf(fmaf(dv, h[j], __ldg(&b3[j])), 0.f);
        r0 = fmaf(hv, __ldg(&Wc[j * 3 + 0]), r0);
        r1 = fmaf(hv, __ldg(&Wc[j * 3 + 1]), r1);
        r2 = fmaf(hv, __ldg(&Wc[j * 3 + 2]), r2);
    }
    out[(size_t)n * 3 + 0] = r0;
    out[(size_t)n * 3 + 1] = r1;
    out[(size_t)n * 3 + 2] = r2;
}

// ---------------- launch ----------------
extern "C" void kernel_launch(void* const* d_in, const int* in_sizes, int n_in,
                              void* d_out, int out_size) {
    const float* latent = (const float*)d_in[0];
    const float* hist   = (const float*)d_in[1];
    const float* subg   = (const float*)d_in[2];
    const void*  ei     = d_in[3];
    const float* W1 = (const float*)d_in[4];
    const float* b1 = (const float*)d_in[5];
    const float* W2 = (const float*)d_in[6];
    const float* b2 = (const float*)d_in[7];
    const float* W3 = (const float*)d_in[8];
    const float* b3 = (const float*)d_in[9];
    const float* Wc = (const float*)d_in[10];
    const float* bc = (const float*)d_in[11];
    float* out = (float*)d_out;

    float *g1, *o1, *g2, *o2, *g3, *o3;
    cudaGetSymbolAddress((void**)&g1, d_g1);
    cudaGetSymbolAddress((void**)&o1, d_o1);
    cudaGetSymbolAddress((void**)&g2, d_g2);
    cudaGetSymbolAddress((void**)&o2, d_o2);
    cudaGetSymbolAddress((void**)&g3, d_g3);
    cudaGetSymbolAddress((void**)&o3, d_o3);

    k_detect<<<1, 32>>>((const int*)ei);
    k_deg_init<<<(NNODES + 255) / 256, 256>>>();
    k_edge_prep<<<(NEDGES + 255) / 256, 256>>>(ei);
    k_dinv<<<(NNODES + 255) / 256, 256>>>();

    const int gblk = (NNODES + 127) / 128;

    // layer 1: K=256 (+2 extra rows), Fout=128
    k_gemm<256, 128, 256, true, false><<<gblk, 256>>>(latent, W1, hist, subg,
                                                      nullptr, g1, o1);
    k_scatter<128><<<(int)(((long long)NEDGES * 32 + 255) / 256), 256>>>(g1, o1);

    // layer 2: K=128, Fout=64, fused relu(dinv*o1+b1) on input
    k_gemm<128, 64, 128, false, true><<<gblk, 128>>>(o1, W2, nullptr, nullptr,
                                                     b1, g2, o2);
    k_scatter<64><<<(int)(((long long)NEDGES * 16 + 255) / 256), 256>>>(g2, o2);

    // layer 3: K=64 -> 8, fused relu(dinv*o2+b2) on input
    k_gemm3<<<(NNODES + 31) / 32, 256>>>(W3, b2);
    k_scatter<8><<<(int)(((long long)NEDGES * 2 + 255) / 256), 256>>>(g3, o3);

    // head (fuses relu-finalize of layer 3)
    k_head<<<(NNODES + 255) / 256, 256>>>(Wc, bc, b3, out);
}

// round 4
// speedup vs baseline: 1.5064x; 1.4518x over previous
#include <cuda_runtime.h>
#include <math.h>

#define NNODES 200000
#define NEDGES 3200000
#define SCAN_BLK 512
#define SCAN_NB ((NNODES + SCAN_BLK - 1) / SCAN_BLK)   // 391

// ---------------- scratch (no allocations allowed) ----------------
__device__ __align__(256) int   d_degi[NNODES];
__device__ __align__(256) float d_dinv[NNODES];
__device__ __align__(256) int   d_src[NEDGES];
__device__ __align__(256) int   d_dst[NEDGES];
__device__ __align__(256) int   d_csr[NEDGES];
__device__ __align__(256) int   d_rowptr[NNODES + 1];
__device__ __align__(256) int   d_cursor[NNODES];
__device__ __align__(256) int   d_bsum[SCAN_NB];
__device__ __align__(256) int   d_boff[SCAN_NB];
__device__ __align__(256) float d_g1[(size_t)NNODES * 128];
__device__ __align__(256) float d_o1[(size_t)NNODES * 128];
__device__ __align__(256) float d_g2[(size_t)NNODES * 64];
__device__ __align__(256) float d_o2[(size_t)NNODES * 64];
__device__ __align__(256) float d_g3[(size_t)NNODES * 8];
__device__ __align__(256) float d_o3[(size_t)NNODES * 8];
__device__ int d_is64;

// ---------------- edge dtype detection ----------------
__global__ void k_detect(const int* __restrict__ ei32) {
    if (threadIdx.x == 0 && blockIdx.x == 0) {
        int zeros = 0;
#pragma unroll
        for (int i = 0; i < 64; i++)
            if (ei32[2 * i + 1] == 0) zeros++;
        d_is64 = (zeros >= 60) ? 1 : 0;
    }
}

// ---------------- degree ----------------
__global__ void k_deg_init() {
    int i = blockIdx.x * blockDim.x + threadIdx.x;
    if (i < NNODES) d_degi[i] = 0;
}

__global__ void k_edge_prep(const void* __restrict__ ei) {
    int e = blockIdx.x * blockDim.x + threadIdx.x;
    if (e >= NEDGES) return;
    int s, d;
    if (d_is64) {
        const long long* p = (const long long*)ei;
        s = (int)p[e];
        d = (int)p[(size_t)NEDGES + e];
    } else {
        const int* p = (const int*)ei;
        s = p[e];
        d = p[NEDGES + e];
    }
    d_src[e] = s;
    d_dst[e] = d;
    atomicAdd(&d_degi[d], 1);
}

__global__ void k_dinv() {
    int i = blockIdx.x * blockDim.x + threadIdx.x;
    if (i < NNODES) d_dinv[i] = rsqrtf((float)(d_degi[i] + 1));  // +1 self-loop
}

// ---------------- 2-level exclusive scan of d_degi -> d_rowptr -------------
__global__ void k_scan1() {
    __shared__ int sh[SCAN_BLK];
    int i = blockIdx.x * SCAN_BLK + threadIdx.x;
    int v = (i < NNODES) ? d_degi[i] : 0;
    sh[threadIdx.x] = v;
    __syncthreads();
    int incl = v;
#pragma unroll
    for (int off = 1; off < SCAN_BLK; off <<= 1) {
        int add = (threadIdx.x >= off) ? sh[threadIdx.x - off] : 0;
        __syncthreads();
        incl += add;
        sh[threadIdx.x] = incl;
        __syncthreads();
    }
    if (i < NNODES) d_rowptr[i] = incl - v;              // block-local exclusive
    if (threadIdx.x == SCAN_BLK - 1) d_bsum[blockIdx.x] = incl;
}

__global__ void k_scan2() {
    __shared__ int sh[SCAN_BLK];
    int t = threadIdx.x;
    int v = (t < SCAN_NB) ? d_bsum[t] : 0;
    sh[t] = v;
    __syncthreads();
    int incl = v;
#pragma unroll
    for (int off = 1; off < SCAN_BLK; off <<= 1) {
        int add = (t >= off) ? sh[t - off] : 0;
        __syncthreads();
        incl += add;
        sh[t] = incl;
        __syncthreads();
    }
    if (t < SCAN_NB) d_boff[t] = incl - v;               // exclusive block offset
}

__global__ void k_scan3() {
    int i = blockIdx.x * blockDim.x + threadIdx.x;
    if (i < NNODES) {
        int r = d_rowptr[i] + d_boff[i / SCAN_BLK];
        d_rowptr[i] = r;
        d_cursor[i] = r;
    }
    if (i == 0) d_rowptr[NNODES] = NEDGES;
}

__global__ void k_csr_fill() {
    int e = blockIdx.x * blockDim.x + threadIdx.x;
    if (e >= NEDGES) return;
    int pos = atomicAdd(&d_cursor[d_dst[e]], 1);
    d_csr[pos] = d_src[e];
}

// ---------------- tiled SIMT GEMM, 8x8 microtile, reg-prefetch -------------
// g = dinv[row] * (Ain[N,K] @ W[K(+2),BN])
template<int K, int BN, int THREADS, bool EXTRA, bool FUSE_IN>
__global__ void __launch_bounds__(THREADS)
k_gemm(const float* __restrict__ A,
       const float* __restrict__ W,
       const float* __restrict__ hist,
       const float* __restrict__ subg,
       const float* __restrict__ bin,
       float* __restrict__ g)
{
    constexpr int BM = 128;
    constexpr int BK = 16;
    constexpr int TM = 8;
    constexpr int TN = 8;
    constexpr int NT = BN / TN;
    static_assert(NT * (BM / TM) == THREADS, "thread shape");
    constexpr int LA = (BM * BK / 4) / THREADS;
    constexpr int LB = (BK * BN / 4) / THREADS;

    __shared__ float As[BK][BM + 4];
    __shared__ float Bs[BK][BN];

    const int tid = threadIdx.x;
    const int tn0 = (tid % NT) * TN;
    const int tm0 = (tid / NT) * TM;
    const int rowBase = blockIdx.x * BM;

    float acc[TM][TN];
#pragma unroll
    for (int i = 0; i < TM; i++)
#pragma unroll
        for (int j = 0; j < TN; j++) acc[i][j] = 0.f;

    int arow[LA], ak4[LA];
#pragma unroll
    for (int u = 0; u < LA; u++) {
        int idx = tid + u * THREADS;
        arow[u] = idx / (BK / 4);
        ak4[u]  = (idx % (BK / 4)) * 4;
    }
    float4 ra[LA], rb[LB];

    auto loadA = [&](int k0) {
#pragma unroll
        for (int u = 0; u < LA; u++) {
            int row = rowBase + arow[u];
            float4 v = make_float4(0.f, 0.f, 0.f, 0.f);
            if (row < NNODES) {
                v = *(const float4*)(A + (size_t)row * K + k0 + ak4[u]);
                if (FUSE_IN) {
                    float dv = d_dinv[row];
                    int kk = k0 + ak4[u];
                    v.x = fmaxf(fmaf(dv, v.x, __ldg(&bin[kk + 0])), 0.f);
                    v.y = fmaxf(fmaf(dv, v.y, __ldg(&bin[kk + 1])), 0.f);
                    v.z = fmaxf(fmaf(dv, v.z, __ldg(&bin[kk + 2])), 0.f);
                    v.w = fmaxf(fmaf(dv, v.w, __ldg(&bin[kk + 3])), 0.f);
                }
            }
            ra[u] = v;
        }
    };
    auto loadB = [&](int k0) {
#pragma unroll
        for (int u = 0; u < LB; u++) {
            int idx = tid + u * THREADS;
            int r = idx / (BN / 4), c4 = (idx % (BN / 4)) * 4;
            rb[u] = *(const float4*)(W + (size_t)(k0 + r) * BN + c4);
        }
    };
    auto stage = [&]() {
#pragma unroll
        for (int u = 0; u < LA; u++) {
            As[ak4[u] + 0][arow[u]] = ra[u].x;
            As[ak4[u] + 1][arow[u]] = ra[u].y;
            As[ak4[u] + 2][arow[u]] = ra[u].z;
            As[ak4[u] + 3][arow[u]] = ra[u].w;
        }
#pragma unroll
        for (int u = 0; u < LB; u++) {
            int idx = tid + u * THREADS;
            int r = idx / (BN / 4), c4 = (idx % (BN / 4)) * 4;
            *(float4*)&Bs[r][c4] = rb[u];
        }
    };

    loadA(0); loadB(0);

    for (int k0 = 0; k0 < K; k0 += BK) {
        stage();
        __syncthreads();
        if (k0 + BK < K) { loadA(k0 + BK); loadB(k0 + BK); }
#pragma unroll
        for (int kk = 0; kk < BK; kk++) {
            float4 a0 = *(const float4*)&As[kk][tm0];
            float4 a1 = *(const float4*)&As[kk][tm0 + 4];
            float4 b0 = *(const float4*)&Bs[kk][tn0];
            float4 b1 = *(const float4*)&Bs[kk][tn0 + 4];
            float av[TM] = {a0.x, a0.y, a0.z, a0.w, a1.x, a1.y, a1.z, a1.w};
            float bv[TN] = {b0.x, b0.y, b0.z, b0.w, b1.x, b1.y, b1.z, b1.w};
#pragma unroll
            for (int i = 0; i < TM; i++)
#pragma unroll
                for (int j = 0; j < TN; j++)
                    acc[i][j] = fmaf(av[i], bv[j], acc[i][j]);
        }
        __syncthreads();
    }

#pragma unroll
    for (int i = 0; i < TM; i++) {
        int row = rowBase + tm0 + i;
        if (row >= NNODES) break;
        float dv = d_dinv[row];
        float hv = 0.f, sv = 0.f;
        if (EXTRA) { hv = hist[row]; sv = subg[row]; }
#pragma unroll
        for (int j4 = 0; j4 < TN; j4 += 4) {
            float4 out4;
            float vals[4];
#pragma unroll
            for (int j = 0; j < 4; j++) {
                float x = acc[i][j4 + j];
                if (EXTRA) {
                    x = fmaf(hv, __ldg(&W[(size_t)K * BN + tn0 + j4 + j]), x);
                    x = fmaf(sv, __ldg(&W[(size_t)(K + 1) * BN + tn0 + j4 + j]), x);
                }
                vals[j] = x * dv;
            }
            out4.x = vals[0]; out4.y = vals[1]; out4.z = vals[2]; out4.w = vals[3];
            *(float4*)(g + (size_t)row * BN + tn0 + j4) = out4;
        }
    }
}

// ------------- CSR pull-gather: o[n] = g[n] + sum_{s in N(n)} g[s] ----------
// GROUP = F/4 lanes per node, each lane owns one float4 column slice.
template<int F, int GROUP>
__global__ void k_gather(const float* __restrict__ g, float* __restrict__ o) {
    const int lane = threadIdx.x & 31;
    const int warp = (blockIdx.x * blockDim.x + threadIdx.x) >> 5;
    constexpr int NPW = 32 / GROUP;                 // nodes per warp
    const int gid  = lane / GROUP;
    const int sub  = lane % GROUP;
    const int base = gid * GROUP;
    const int node = warp * NPW + gid;
    const bool valid = node < NNODES;

    int beg = valid ? __ldg(&d_rowptr[node])     : 0;
    int end = valid ? __ldg(&d_rowptr[node + 1]) : 0;
    int len = end - beg;

    float4 acc = make_float4(0.f, 0.f, 0.f, 0.f);
    if (valid)
        acc = __ldg((const float4*)(g + (size_t)node * F) + sub);   // self-loop

    // warp-uniform trip count so shfl stays converged
    int maxlen = len;
#pragma unroll
    for (int off = 16; off; off >>= 1)
        maxlen = max(maxlen, __shfl_xor_sync(0xffffffffu, maxlen, off));

    int s_pre = 0;
    for (int t = 0; t < maxlen; t++) {
        if ((t % GROUP) == 0) {
            int j = beg + t + sub;
            s_pre = (j < end) ? __ldg(&d_csr[j]) : 0;
        }
        int ss = __shfl_sync(0xffffffffu, s_pre, base + (t % GROUP));
        if (t < len) {
            float4 v = __ldg((const float4*)(g + (size_t)ss * F) + sub);
            acc.x += v.x; acc.y += v.y; acc.z += v.z; acc.w += v.w;
        }
    }
    if (valid)
        *((float4*)(o + (size_t)node * F) + sub) = acc;
}

// ------- layer 3 GEMM: [N,64] -> [N,8], fused input relu + dinv scale ------
__global__ void __launch_bounds__(256) k_gemm3(const float* __restrict__ W3,
                                               const float* __restrict__ b2) {
    __shared__ float Ws[64 * 8];
    __shared__ float Bb[64];
    __shared__ float Hs[32][65];
    int tid = threadIdx.x;
    for (int i = tid; i < 512; i += 256) Ws[i] = W3[i];
    if (tid < 64) Bb[tid] = b2[tid];
    int nodeBase = blockIdx.x * 32;
    __syncthreads();
    for (int i = tid; i < 512; i += 256) {
        int r = i / 16, c4 = i % 16;
        int node = nodeBase + r;
        if (node < NNODES) {
            float dv = d_dinv[node];
            float4 v = *(const float4*)(d_o2 + (size_t)node * 64 + c4 * 4);
            Hs[r][c4 * 4 + 0] = fmaxf(fmaf(dv, v.x, Bb[c4 * 4 + 0]), 0.f);
            Hs[r][c4 * 4 + 1] = fmaxf(fmaf(dv, v.y, Bb[c4 * 4 + 1]), 0.f);
            Hs[r][c4 * 4 + 2] = fmaxf(fmaf(dv, v.z, Bb[c4 * 4 + 2]), 0.f);
            Hs[r][c4 * 4 + 3] = fmaxf(fmaf(dv, v.w, Bb[c4 * 4 + 3]), 0.f);
        }
    }
    __syncthreads();
    int ln = tid / 8, col = tid % 8;
    int node = nodeBase + ln;
    if (node >= NNODES) return;
    float acc = 0.f;
#pragma unroll
    for (int k = 0; k < 64; k++) acc = fmaf(Hs[ln][k], Ws[k * 8 + col], acc);
    d_g3[(size_t)node * 8 + col] = d_dinv[node] * acc;
}

// ---------------- final head: relu(dinv*o3+b3) @ Wc + bc ----------------
__global__ void k_head(const float* __restrict__ Wc, const float* __restrict__ bc,
                       const float* __restrict__ b3, float* __restrict__ out) {
    int n = blockIdx.x * blockDim.x + threadIdx.x;
    if (n >= NNODES) return;
    float dv = d_dinv[n];
    float4 p0 = *(const float4*)(d_o3 + (size_t)n * 8);
    float4 p1 = *(const float4*)(d_o3 + (size_t)n * 8 + 4);
    float h[8] = {p0.x, p0.y, p0.z, p0.w, p1.x, p1.y, p1.z, p1.w};
    float r0 = __ldg(&bc[0]), r1 = __ldg(&bc[1]), r2 = __ldg(&bc[2]);
#pragma unroll
    for (int j = 0; j < 8; j++) {
        float hv = fmaxf(fmaf(dv, h[j], __ldg(&b3[j])), 0.f);
        r0 = fmaf(hv, __ldg(&Wc[j * 3 + 0]), r0);
        r1 = fmaf(hv, __ldg(&Wc[j * 3 + 1]), r1);
        r2 = fmaf(hv, __ldg(&Wc[j * 3 + 2]), r2);
    }
    out[(size_t)n * 3 + 0] = r0;
    out[(size_t)n * 3 + 1] = r1;
    out[(size_t)n * 3 + 2] = r2;
}

// ---------------- launch ----------------
extern "C" void kernel_launch(void* const* d_in, const int* in_sizes, int n_in,
                              void* d_out, int out_size) {
    const float* latent = (const float*)d_in[0];
    const float* hist   = (const float*)d_in[1];
    const float* subg   = (const float*)d_in[2];
    const void*  ei     = d_in[3];
    const float* W1 = (const float*)d_in[4];
    const float* b1 = (const float*)d_in[5];
    const float* W2 = (const float*)d_in[6];
    const float* b2 = (const float*)d_in[7];
    const float* W3 = (const float*)d_in[8];
    const float* b3 = (const float*)d_in[9];
    const float* Wc = (const float*)d_in[10];
    const float* bc = (const float*)d_in[11];
    float* out = (float*)d_out;

    float *g1, *o1, *g2, *o2, *g3, *o3;
    cudaGetSymbolAddress((void**)&g1, d_g1);
    cudaGetSymbolAddress((void**)&o1, d_o1);
    cudaGetSymbolAddress((void**)&g2, d_g2);
    cudaGetSymbolAddress((void**)&o2, d_o2);
    cudaGetSymbolAddress((void**)&g3, d_g3);
    cudaGetSymbolAddress((void**)&o3, d_o3);

    const int gblk = (NNODES + 127) / 128;

    // launches 0..4, then GEMM1 at index 5 (ncu -s 5 profiles it)
    k_detect<<<1, 32>>>((const int*)ei);                               // 0
    k_deg_init<<<(NNODES + 255) / 256, 256>>>();                       // 1
    k_edge_prep<<<(NEDGES + 255) / 256, 256>>>(ei);                    // 2
    k_dinv<<<(NNODES + 255) / 256, 256>>>();                           // 3
    k_scan1<<<SCAN_NB, SCAN_BLK>>>();                                  // 4
    k_gemm<256, 128, 256, true, false><<<gblk, 256>>>(latent, W1,      // 5
                                                      hist, subg, nullptr, g1);
    k_scan2<<<1, SCAN_BLK>>>();                                        // 6
    k_scan3<<<(NNODES + 255) / 256, 256>>>();                          // 7
    k_csr_fill<<<(NEDGES + 255) / 256, 256>>>();                       // 8

    // layer 1 aggregate: F=128, one node per warp
    k_gather<128, 32><<<(NNODES * 32 + 255) / 256, 256>>>(g1, o1);

    // layer 2: K=128 -> 64, fused relu(dinv*o1+b1) on input
    k_gemm<128, 64, 128, false, true><<<gblk, 128>>>(o1, W2, nullptr, nullptr,
                                                     b1, g2);
    k_gather<64, 16><<<(NNODES * 16 + 255) / 256, 256>>>(g2, o2);

    // layer 3: 64 -> 8, fused relu(dinv*o2+b2) on input
    k_gemm3<<<(NNODES + 31) / 32, 256>>>(W3, b2);
    k_gather<8, 2><<<(NNODES * 2 + 255) / 256, 256>>>(g3, o3);

    // head (fuses relu-finalize of layer 3)
    k_head<<<(NNODES + 255) / 256, 256>>>(Wc, bc, b3, out);
}

// round 7
// speedup vs baseline: 1.8040x; 1.1976x over previous
#include <cuda_runtime.h>
#include <cuda_bf16.h>
#include <math.h>
#include <stdint.h>

#define NNODES 200000
#define NEDGES 3200000
#define SCAN_BLK 512
#define SCAN_NB ((NNODES + SCAN_BLK - 1) / SCAN_BLK)   // 391

// ---------------- scratch (no allocations allowed) ----------------
__device__ __align__(256) int   d_degi[NNODES];
__device__ __align__(256) float d_dinv[NNODES];
__device__ __align__(256) int   d_csr[NEDGES];
__device__ __align__(256) int   d_rowptr[NNODES + 1];
__device__ __align__(256) int   d_cursor[NNODES];
__device__ __align__(256) int   d_bsum[SCAN_NB];
__device__ __align__(256) int   d_boff[SCAN_NB];
__device__ __align__(256) unsigned short d_w1hi[256 * 128];  // [k][n] bf16
__device__ __align__(256) unsigned short d_w1lo[256 * 128];
__device__ __align__(256) float d_g1[(size_t)NNODES * 128];
__device__ __align__(256) float d_o1[(size_t)NNODES * 128];
__device__ __align__(256) float d_g2[(size_t)NNODES * 64];
__device__ __align__(256) float d_o2[(size_t)NNODES * 64];
__device__ __align__(256) float d_g3[(size_t)NNODES * 8];
__device__ __align__(256) float d_o3[(size_t)NNODES * 8];
__device__ int d_is64;

// ---------------- PTX helpers (baseline ISA only, sm_103-safe) -------------
__device__ __forceinline__ uint32_t smem_u32(const void* p) {
    uint32_t a;
    asm("{ .reg .u64 t; cvta.to.shared.u64 t, %1; cvt.u32.u64 %0, t; }"
        : "=r"(a) : "l"(p));
    return a;
}
__device__ __forceinline__ void ldmx4(uint32_t* r, uint32_t addr) {
    asm volatile("ldmatrix.sync.aligned.m8n8.x4.shared.b16 {%0,%1,%2,%3}, [%4];"
                 : "=r"(r[0]), "=r"(r[1]), "=r"(r[2]), "=r"(r[3]) : "r"(addr));
}
__device__ __forceinline__ void ldmx4t(uint32_t* r, uint32_t addr) {
    asm volatile("ldmatrix.sync.aligned.m8n8.x4.trans.shared.b16 {%0,%1,%2,%3}, [%4];"
                 : "=r"(r[0]), "=r"(r[1]), "=r"(r[2]), "=r"(r[3]) : "r"(addr));
}
__device__ __forceinline__ void mma16816(float* d, const uint32_t* a, const uint32_t* b) {
    asm volatile("mma.sync.aligned.m16n8k16.row.col.f32.bf16.bf16.f32 "
                 "{%0,%1,%2,%3}, {%4,%5,%6,%7}, {%8,%9}, {%0,%1,%2,%3};"
                 : "+f"(d[0]), "+f"(d[1]), "+f"(d[2]), "+f"(d[3])
                 : "r"(a[0]), "r"(a[1]), "r"(a[2]), "r"(a[3]),
                   "r"(b[0]), "r"(b[1]));
}
__device__ __forceinline__ void cvt_split(float x, unsigned short& hi, unsigned short& lo) {
    __nv_bfloat16 h = __float2bfloat16_rn(x);
    hi = __bfloat16_as_ushort(h);
    lo = __bfloat16_as_ushort(__float2bfloat16_rn(x - __bfloat162float(h)));
}

// ---------------- edge dtype detection ----------------
__global__ void k_detect(const int* __restrict__ ei32) {
    if (threadIdx.x == 0 && blockIdx.x == 0) {
        int zeros = 0;
#pragma unroll
        for (int i = 0; i < 64; i++)
            if (ei32[2 * i + 1] == 0) zeros++;
        d_is64 = (zeros >= 60) ? 1 : 0;
    }
}

__global__ void k_deg_init() {
    int i = blockIdx.x * blockDim.x + threadIdx.x;
    if (i < NNODES) d_degi[i] = 0;
}

__global__ void k_edge_prep(const void* __restrict__ ei) {   // degree over dst
    int e = blockIdx.x * blockDim.x + threadIdx.x;
    if (e >= NEDGES) return;
    int d = d_is64 ? (int)((const long long*)ei)[(size_t)NEDGES + e]
                   : ((const int*)ei)[NEDGES + e];
    atomicAdd(&d_degi[d], 1);
}

__global__ void k_dinv() {
    int i = blockIdx.x * blockDim.x + threadIdx.x;
    if (i < NNODES) d_dinv[i] = rsqrtf((float)(d_degi[i] + 1));
}

// ---------------- W1 -> bf16 hi/lo planes, [k][n] layout ----------------
__global__ void k_wprep(const float* __restrict__ W1) {
    int idx = blockIdx.x * blockDim.x + threadIdx.x;   // k*128+n, k<256
    if (idx >= 256 * 128) return;
    unsigned short hi, lo;
    cvt_split(W1[idx], hi, lo);
    d_w1hi[idx] = hi;
    d_w1lo[idx] = lo;
}

// ---------------- scan -> rowptr ----------------
__global__ void k_scan1() {
    __shared__ int sh[SCAN_BLK];
    int i = blockIdx.x * SCAN_BLK + threadIdx.x;
    int v = (i < NNODES) ? d_degi[i] : 0;
    sh[threadIdx.x] = v;
    __syncthreads();
    int incl = v;
#pragma unroll
    for (int off = 1; off < SCAN_BLK; off <<= 1) {
        int add = (threadIdx.x >= off) ? sh[threadIdx.x - off] : 0;
        __syncthreads();
        incl += add;
        sh[threadIdx.x] = incl;
        __syncthreads();
    }
    if (i < NNODES) d_rowptr[i] = incl - v;
    if (threadIdx.x == SCAN_BLK - 1) d_bsum[blockIdx.x] = incl;
}
__global__ void k_scan2() {
    __shared__ int sh[SCAN_BLK];
    int t = threadIdx.x;
    int v = (t < SCAN_NB) ? d_bsum[t] : 0;
    sh[t] = v;
    __syncthreads();
    int incl = v;
#pragma unroll
    for (int off = 1; off < SCAN_BLK; off <<= 1) {
        int add = (t >= off) ? sh[t - off] : 0;
        __syncthreads();
        incl += add;
        sh[t] = incl;
        __syncthreads();
    }
    if (t < SCAN_NB) d_boff[t] = incl - v;
}
__global__ void k_scan3() {
    int i = blockIdx.x * blockDim.x + threadIdx.x;
    if (i < NNODES) {
        int r = d_rowptr[i] + d_boff[i / SCAN_BLK];
        d_rowptr[i] = r;
        d_cursor[i] = r;
    }
    if (i == 0) d_rowptr[NNODES] = NEDGES;
}
__global__ void k_csr_fill(const void* __restrict__ ei) {
    int e = blockIdx.x * blockDim.x + threadIdx.x;
    if (e >= NEDGES) return;
    int s, d;
    if (d_is64) {
        const long long* p = (const long long*)ei;
        s = (int)p[e];
        d = (int)p[(size_t)NEDGES + e];
    } else {
        const int* p = (const int*)ei;
        s = p[e];
        d = p[NEDGES + e];
    }
    int pos = atomicAdd(&d_cursor[d], 1);
    d_csr[pos] = s;
}

// ========== GEMM1: mma.sync bf16-split, 128x128 tile, K=256 ==========
// g1[row] = dinv[row]*(latent[row] @ W1[0:256] + hist*W1[256] + subg*W1[257])
#define APAD 40    // bf16 per A smem row (32 data + 8 pad)
#define BPAD 136   // bf16 per B smem row (128 data + 8 pad)
__global__ void __launch_bounds__(256)
k_gemm1_mma(const float* __restrict__ A, const float* __restrict__ W1,
            const float* __restrict__ hist, const float* __restrict__ subg,
            float* __restrict__ g) {
    __shared__ __align__(16) unsigned short sAh[128][APAD];
    __shared__ __align__(16) unsigned short sAl[128][APAD];
    __shared__ __align__(16) unsigned short sBh[32][BPAD];
    __shared__ __align__(16) unsigned short sBl[32][BPAD];

    const int tid = threadIdx.x;
    const int wid = tid >> 5, lane = tid & 31;
    const int rowBase = blockIdx.x * 128;
    const int mbase = (wid >> 1) * 32;         // 0,32,64,96
    const int nbase = (wid & 1) * 64;          // 0,64

    float acc[2][8][4];
#pragma unroll
    for (int i = 0; i < 2; i++)
#pragma unroll
        for (int j = 0; j < 8; j++)
#pragma unroll
            for (int q = 0; q < 4; q++) acc[i][j][q] = 0.f;

    const int aRow = lane & 15, aK = (lane >> 4) * 8;
    const int bK = lane & 15, bN = (lane >> 4) * 8;

    for (int c = 0; c < 8; c++) {
        const int k0 = c * 32;
        // A: 128 rows x 32 fp32 -> bf16 hi/lo   (1024 float4)
#pragma unroll
        for (int t = 0; t < 4; t++) {
            int idx = tid + t * 256;
            int m = idx >> 3, f4 = idx & 7;
            int row = rowBase + m;
            float4 v = make_float4(0.f, 0.f, 0.f, 0.f);
            if (row < NNODES)
                v = *(const float4*)(A + (size_t)row * 256 + k0 + f4 * 4);
            unsigned short h0, h1, h2, h3, l0, l1, l2, l3;
            cvt_split(v.x, h0, l0); cvt_split(v.y, h1, l1);
            cvt_split(v.z, h2, l2); cvt_split(v.w, h3, l3);
            uint2 hh, ll;
            hh.x = (uint32_t)h0 | ((uint32_t)h1 << 16);
            hh.y = (uint32_t)h2 | ((uint32_t)h3 << 16);
            ll.x = (uint32_t)l0 | ((uint32_t)l1 << 16);
            ll.y = (uint32_t)l2 | ((uint32_t)l3 << 16);
            *(uint2*)&sAh[m][f4 * 4] = hh;
            *(uint2*)&sAl[m][f4 * 4] = ll;
        }
        // B: 32 k-rows x 128 n (= 16 uint4 per row, 512 uint4 per plane)
#pragma unroll
        for (int t = 0; t < 2; t++) {
            int idx = tid + t * 256;           // 0..511
            int k = idx >> 4;                  // 0..31
            int u = idx & 15;                  // 0..15
            *(uint4*)&sBh[k][u * 8] = *(const uint4*)(d_w1hi + (size_t)(k0 + k) * 128 + u * 8);
            *(uint4*)&sBl[k][u * 8] = *(const uint4*)(d_w1lo + (size_t)(k0 + k) * 128 + u * 8);
        }
        __syncthreads();

#pragma unroll
        for (int ks = 0; ks < 32; ks += 16) {
            uint32_t ah[2][4], al[2][4], bh[4][4], bl[4][4];
#pragma unroll
            for (int mt = 0; mt < 2; mt++) {
                ldmx4(ah[mt], smem_u32(&sAh[mbase + mt * 16 + aRow][ks + aK]));
                ldmx4(al[mt], smem_u32(&sAl[mbase + mt * 16 + aRow][ks + aK]));
            }
#pragma unroll
            for (int ng = 0; ng < 4; ng++) {
                ldmx4t(bh[ng], smem_u32(&sBh[ks + bK][nbase + ng * 16 + bN]));
                ldmx4t(bl[ng], smem_u32(&sBl[ks + bK][nbase + ng * 16 + bN]));
            }
#pragma unroll
            for (int mt = 0; mt < 2; mt++)
#pragma unroll
                for (int ng = 0; ng < 4; ng++) {
                    mma16816(acc[mt][ng * 2 + 0], ah[mt], &bh[ng][0]);
                    mma16816(acc[mt][ng * 2 + 0], ah[mt], &bl[ng][0]);
                    mma16816(acc[mt][ng * 2 + 0], al[mt], &bh[ng][0]);
                    mma16816(acc[mt][ng * 2 + 1], ah[mt], &bh[ng][2]);
                    mma16816(acc[mt][ng * 2 + 1], ah[mt], &bl[ng][2]);
                    mma16816(acc[mt][ng * 2 + 1], al[mt], &bh[ng][2]);
                }
        }
        __syncthreads();
    }

    // epilogue: x = acc + hv*W1[256] + sv*W1[257]; g = x*dinv
#pragma unroll
    for (int mt = 0; mt < 2; mt++) {
        int r0 = rowBase + mbase + mt * 16 + (lane >> 2);
        int r1 = r0 + 8;
        float dv0 = 0.f, hv0 = 0.f, sv0 = 0.f, dv1 = 0.f, hv1 = 0.f, sv1 = 0.f;
        if (r0 < NNODES) { dv0 = d_dinv[r0]; hv0 = hist[r0]; sv0 = subg[r0]; }
        if (r1 < NNODES) { dv1 = d_dinv[r1]; hv1 = hist[r1]; sv1 = subg[r1]; }
#pragma unroll
        for (int nt = 0; nt < 8; nt++) {
            int col = nbase + nt * 8 + (lane & 3) * 2;
            float w2a = __ldg(&W1[(size_t)256 * 128 + col]);
            float w2b = __ldg(&W1[(size_t)256 * 128 + col + 1]);
            float w3a = __ldg(&W1[(size_t)257 * 128 + col]);
            float w3b = __ldg(&W1[(size_t)257 * 128 + col + 1]);
            if (r0 < NNODES) {
                float2 o;
                o.x = (acc[mt][nt][0] + hv0 * w2a + sv0 * w3a) * dv0;
                o.y = (acc[mt][nt][1] + hv0 * w2b + sv0 * w3b) * dv0;
                *(float2*)(g + (size_t)r0 * 128 + col) = o;
            }
            if (r1 < NNODES) {
                float2 o;
                o.x = (acc[mt][nt][2] + hv1 * w2a + sv1 * w3a) * dv1;
                o.y = (acc[mt][nt][3] + hv1 * w2b + sv1 * w3b) * dv1;
                *(float2*)(g + (size_t)r1 * 128 + col) = o;
            }
        }
    }
}

// ---------------- SIMT GEMM (layer 2), fused input relu ----------------
template<int K, int BN, int THREADS, bool FUSE_IN>
__global__ void __launch_bounds__(THREADS)
k_gemm(const float* __restrict__ A, const float* __restrict__ W,
       const float* __restrict__ bin, float* __restrict__ g) {
    constexpr int BM = 128, BK = 16, TM = 8, TN = 8;
    constexpr int NT = BN / TN;
    static_assert(NT * (BM / TM) == THREADS, "thread shape");
    constexpr int LA = (BM * BK / 4) / THREADS;
    constexpr int LB = (BK * BN / 4) / THREADS;

    __shared__ __align__(16) float As[BK][BM + 4];
    __shared__ __align__(16) float Bs[BK][BN];

    const int tid = threadIdx.x;
    const int tn0 = (tid % NT) * TN;
    const int tm0 = (tid / NT) * TM;
    const int rowBase = blockIdx.x * BM;

    float acc[TM][TN];
#pragma unroll
    for (int i = 0; i < TM; i++)
#pragma unroll
        for (int j = 0; j < TN; j++) acc[i][j] = 0.f;

    int arow[LA], ak4[LA];
#pragma unroll
    for (int u = 0; u < LA; u++) {
        int idx = tid + u * THREADS;
        arow[u] = idx / (BK / 4);
        ak4[u]  = (idx % (BK / 4)) * 4;
    }
    float4 ra[LA], rb[LB];

    auto loadA = [&](int k0) {
#pragma unroll
        for (int u = 0; u < LA; u++) {
            int row = rowBase + arow[u];
            float4 v = make_float4(0.f, 0.f, 0.f, 0.f);
            if (row < NNODES) {
                v = *(const float4*)(A + (size_t)row * K + k0 + ak4[u]);
                if (FUSE_IN) {
                    float dv = d_dinv[row];
                    int kk = k0 + ak4[u];
                    v.x = fmaxf(fmaf(dv, v.x, __ldg(&bin[kk + 0])), 0.f);
                    v.y = fmaxf(fmaf(dv, v.y, __ldg(&bin[kk + 1])), 0.f);
                    v.z = fmaxf(fmaf(dv, v.z, __ldg(&bin[kk + 2])), 0.f);
                    v.w = fmaxf(fmaf(dv, v.w, __ldg(&bin[kk + 3])), 0.f);
                }
            }
            ra[u] = v;
        }
    };
    auto loadB = [&](int k0) {
#pragma unroll
        for (int u = 0; u < LB; u++) {
            int idx = tid + u * THREADS;
            int r = idx / (BN / 4), c4 = (idx % (BN / 4)) * 4;
            rb[u] = *(const float4*)(W + (size_t)(k0 + r) * BN + c4);
        }
    };
    auto stage = [&]() {
#pragma unroll
        for (int u = 0; u < LA; u++) {
            As[ak4[u] + 0][arow[u]] = ra[u].x;
            As[ak4[u] + 1][arow[u]] = ra[u].y;
            As[ak4[u] + 2][arow[u]] = ra[u].z;
            As[ak4[u] + 3][arow[u]] = ra[u].w;
        }
#pragma unroll
        for (int u = 0; u < LB; u++) {
            int idx = tid + u * THREADS;
            int r = idx / (BN / 4), c4 = (idx % (BN / 4)) * 4;
            *(float4*)&Bs[r][c4] = rb[u];
        }
    };

    loadA(0); loadB(0);
    for (int k0 = 0; k0 < K; k0 += BK) {
        stage();
        __syncthreads();
        if (k0 + BK < K) { loadA(k0 + BK); loadB(k0 + BK); }
#pragma unroll
        for (int kk = 0; kk < BK; kk++) {
            float4 a0 = *(const float4*)&As[kk][tm0];
            float4 a1 = *(const float4*)&As[kk][tm0 + 4];
            float4 b0 = *(const float4*)&Bs[kk][tn0];
            float4 b1 = *(const float4*)&Bs[kk][tn0 + 4];
            float av[TM] = {a0.x, a0.y, a0.z, a0.w, a1.x, a1.y, a1.z, a1.w};
            float bv[TN] = {b0.x, b0.y, b0.z, b0.w, b1.x, b1.y, b1.z, b1.w};
#pragma unroll
            for (int i = 0; i < TM; i++)
#pragma unroll
                for (int j = 0; j < TN; j++)
                    acc[i][j] = fmaf(av[i], bv[j], acc[i][j]);
        }
        __syncthreads();
    }

#pragma unroll
    for (int i = 0; i < TM; i++) {
        int row = rowBase + tm0 + i;
        if (row >= NNODES) break;
        float dv = d_dinv[row];
#pragma unroll
        for (int j4 = 0; j4 < TN; j4 += 4) {
            float4 out4;
            out4.x = acc[i][j4 + 0] * dv;
            out4.y = acc[i][j4 + 1] * dv;
            out4.z = acc[i][j4 + 2] * dv;
            out4.w = acc[i][j4 + 3] * dv;
            *(float4*)(g + (size_t)row * BN + tn0 + j4) = out4;
        }
    }
}

// ------------- CSR pull-gather ----------
template<int F, int GROUP>
__global__ void k_gather(const float* __restrict__ g, float* __restrict__ o) {
    const int lane = threadIdx.x & 31;
    const int warp = (blockIdx.x * blockDim.x + threadIdx.x) >> 5;
    constexpr int NPW = 32 / GROUP;
    const int gid  = lane / GROUP;
    const int sub  = lane % GROUP;
    const int base = gid * GROUP;
    const int node = warp * NPW + gid;
    const bool valid = node < NNODES;

    int beg = valid ? __ldg(&d_rowptr[node])     : 0;
    int end = valid ? __ldg(&d_rowptr[node + 1]) : 0;
    int len = end - beg;

    float4 acc = make_float4(0.f, 0.f, 0.f, 0.f);
    if (valid)
        acc = __ldg((const float4*)(g + (size_t)node * F) + sub);

    int maxlen = len;
#pragma unroll
    for (int off = 16; off; off >>= 1)
        maxlen = max(maxlen, __shfl_xor_sync(0xffffffffu, maxlen, off));

    int s_pre = 0;
    for (int t = 0; t < maxlen; t++) {
        if ((t % GROUP) == 0) {
            int j = beg + t + sub;
            s_pre = (j < end) ? __ldg(&d_csr[j]) : 0;
        }
        int ss = __shfl_sync(0xffffffffu, s_pre, base + (t % GROUP));
        if (t < len) {
            float4 v = __ldg((const float4*)(g + (size_t)ss * F) + sub);
            acc.x += v.x; acc.y += v.y; acc.z += v.z; acc.w += v.w;
        }
    }
    if (valid)
        *((float4*)(o + (size_t)node * F) + sub) = acc;
}

// ------- layer 3 GEMM ------
__global__ void __launch_bounds__(256) k_gemm3(const float* __restrict__ W3,
                                               const float* __restrict__ b2) {
    __shared__ float Ws[64 * 8];
    __shared__ float Bb[64];
    __shared__ __align__(16) float Hs[32][65];
    int tid = threadIdx.x;
    for (int i = tid; i < 512; i += 256) Ws[i] = W3[i];
    if (tid < 64) Bb[tid] = b2[tid];
    int nodeBase = blockIdx.x * 32;
    __syncthreads();
    for (int i = tid; i < 512; i += 256) {
        int r = i / 16, c4 = i % 16;
        int node = nodeBase + r;
        if (node < NNODES) {
            float dv = d_dinv[node];
            float4 v = *(const float4*)(d_o2 + (size_t)node * 64 + c4 * 4);
            Hs[r][c4 * 4 + 0] = fmaxf(fmaf(dv, v.x, Bb[c4 * 4 + 0]), 0.f);
            Hs[r][c4 * 4 + 1] = fmaxf(fmaf(dv, v.y, Bb[c4 * 4 + 1]), 0.f);
            Hs[r][c4 * 4 + 2] = fmaxf(fmaf(dv, v.z, Bb[c4 * 4 + 2]), 0.f);
            Hs[r][c4 * 4 + 3] = fmaxf(fmaf(dv, v.w, Bb[c4 * 4 + 3]), 0.f);
        }
    }
    __syncthreads();
    int ln = tid / 8, col = tid % 8;
    int node = nodeBase + ln;
    if (node >= NNODES) return;
    float acc = 0.f;
#pragma unroll
    for (int k = 0; k < 64; k++) acc = fmaf(Hs[ln][k], Ws[k * 8 + col], acc);
    d_g3[(size_t)node * 8 + col] = d_dinv[node] * acc;
}

// ---------------- final head ----------------
__global__ void k_head(const float* __restrict__ Wc, const float* __restrict__ bc,
                       const float* __restrict__ b3, float* __restrict__ out) {
    int n = blockIdx.x * blockDim.x + threadIdx.x;
    if (n >= NNODES) return;
    float dv = d_dinv[n];
    float4 p0 = *(const float4*)(d_o3 + (size_t)n * 8);
    float4 p1 = *(const float4*)(d_o3 + (size_t)n * 8 + 4);
    float h[8] = {p0.x, p0.y, p0.z, p0.w, p1.x, p1.y, p1.z, p1.w};
    float r0 = __ldg(&bc[0]), r1 = __ldg(&bc[1]), r2 = __ldg(&bc[2]);
#pragma unroll
    for (int j = 0; j < 8; j++) {
        float hv = fmaxf(fmaf(dv, h[j], __ldg(&b3[j])), 0.f);
        r0 = fmaf(hv, __ldg(&Wc[j * 3 + 0]), r0);
        r1 = fmaf(hv, __ldg(&Wc[j * 3 + 1]), r1);
        r2 = fmaf(hv, __ldg(&Wc[j * 3 + 2]), r2);
    }
    out[(size_t)n * 3 + 0] = r0;
    out[(size_t)n * 3 + 1] = r1;
    out[(size_t)n * 3 + 2] = r2;
}

// ---------------- launch ----------------
extern "C" void kernel_launch(void* const* d_in, const int* in_sizes, int n_in,
                              void* d_out, int out_size) {
    const float* latent = (const float*)d_in[0];
    const float* hist   = (const float*)d_in[1];
    const float* subg   = (const float*)d_in[2];
    const void*  ei     = d_in[3];
    const float* W1 = (const float*)d_in[4];
    const float* b1 = (const float*)d_in[5];
    const float* W2 = (const float*)d_in[6];
    const float* b2 = (const float*)d_in[7];
    const float* W3 = (const float*)d_in[8];
    const float* b3 = (const float*)d_in[9];
    const float* Wc = (const float*)d_in[10];
    const float* bc = (const float*)d_in[11];
    float* out = (float*)d_out;

    float *g1, *o1, *g2, *o2, *g3, *o3;
    cudaGetSymbolAddress((void**)&g1, d_g1);
    cudaGetSymbolAddress((void**)&o1, d_o1);
    cudaGetSymbolAddress((void**)&g2, d_g2);
    cudaGetSymbolAddress((void**)&o2, d_o2);
    cudaGetSymbolAddress((void**)&g3, d_g3);
    cudaGetSymbolAddress((void**)&o3, d_o3);

    k_detect<<<1, 32>>>((const int*)ei);
    k_deg_init<<<(NNODES + 255) / 256, 256>>>();
    k_edge_prep<<<(NEDGES + 255) / 256, 256>>>(ei);
    k_dinv<<<(NNODES + 255) / 256, 256>>>();
    k_wprep<<<(256 * 128 + 255) / 256, 256>>>(W1);

    // GEMM1 on tensor cores (mma.sync bf16-split)
    k_gemm1_mma<<<(NNODES + 127) / 128, 256>>>(latent, W1, hist, subg, g1);

    // CSR build
    k_scan1<<<SCAN_NB, SCAN_BLK>>>();
    k_scan2<<<1, SCAN_BLK>>>();
    k_scan3<<<(NNODES + 255) / 256, 256>>>();
    k_csr_fill<<<(NEDGES + 255) / 256, 256>>>(ei);

    // layer 1 aggregate
    k_gather<128, 32><<<(NNODES * 32 + 255) / 256, 256>>>(g1, o1);

    // layer 2: K=128 -> 64, fused relu(dinv*o1+b1) on input
    k_gemm<128, 64, 128, true><<<(NNODES + 127) / 128, 128>>>(o1, W2, b1, g2);
    k_gather<64, 16><<<(NNODES * 16 + 255) / 256, 256>>>(g2, o2);

    // layer 3: 64 -> 8
    k_gemm3<<<(NNODES + 31) / 32, 256>>>(W3, b2);
    k_gather<8, 2><<<(NNODES * 2 + 255) / 256, 256>>>(g3, o3);

    k_head<<<(NNODES + 255) / 256, 256>>>(Wc, bc, b3, out);
}

// round 8
// speedup vs baseline: 2.2826x; 1.2653x over previous
#include <cuda_runtime.h>
#include <cuda_bf16.h>
#include <cuda_fp16.h>
#include <math.h>
#include <stdint.h>

#define NNODES 200000
#define NEDGES 3200000
#define SCAN_BLK 512
#define SCAN_NB ((NNODES + SCAN_BLK - 1) / SCAN_BLK)   // 391

// ---------------- scratch (no allocations allowed) ----------------
__device__ __align__(256) int   d_degi[NNODES];
__device__ __align__(256) float d_dinv[NNODES];
__device__ __align__(256) int   d_csr[NEDGES];
__device__ __align__(256) int   d_rowptr[NNODES + 1];
__device__ __align__(256) int   d_cursor[NNODES];
__device__ __align__(256) int   d_bsum[SCAN_NB];
__device__ __align__(256) int   d_boff[SCAN_NB];
__device__ __align__(256) unsigned short d_w1hi[256 * 128];  // [k][n] bf16
__device__ __align__(256) unsigned short d_w1lo[256 * 128];
__device__ __align__(256) unsigned short d_w2hi[128 * 64];   // [k][n] bf16
__device__ __align__(256) unsigned short d_w2lo[128 * 64];
__device__ __align__(256) __half d_g1h[(size_t)NNODES * 128];
__device__ __align__(256) float d_o1[(size_t)NNODES * 128];
__device__ __align__(256) float d_g2[(size_t)NNODES * 64];
__device__ __align__(256) float d_o2[(size_t)NNODES * 64];
__device__ __align__(256) float d_g3[(size_t)NNODES * 8];
__device__ __align__(256) float d_o3[(size_t)NNODES * 8];
__device__ int d_is64;

// ---------------- PTX helpers (baseline ISA only, sm_103-safe) -------------
__device__ __forceinline__ uint32_t smem_u32(const void* p) {
    uint32_t a;
    asm("{ .reg .u64 t; cvta.to.shared.u64 t, %1; cvt.u32.u64 %0, t; }"
        : "=r"(a) : "l"(p));
    return a;
}
__device__ __forceinline__ void ldmx4(uint32_t* r, uint32_t addr) {
    asm volatile("ldmatrix.sync.aligned.m8n8.x4.shared.b16 {%0,%1,%2,%3}, [%4];"
                 : "=r"(r[0]), "=r"(r[1]), "=r"(r[2]), "=r"(r[3]) : "r"(addr));
}
__device__ __forceinline__ void ldmx4t(uint32_t* r, uint32_t addr) {
    asm volatile("ldmatrix.sync.aligned.m8n8.x4.trans.shared.b16 {%0,%1,%2,%3}, [%4];"
                 : "=r"(r[0]), "=r"(r[1]), "=r"(r[2]), "=r"(r[3]) : "r"(addr));
}
__device__ __forceinline__ void mma16816(float* d, const uint32_t* a, const uint32_t* b) {
    asm volatile("mma.sync.aligned.m16n8k16.row.col.f32.bf16.bf16.f32 "
                 "{%0,%1,%2,%3}, {%4,%5,%6,%7}, {%8,%9}, {%0,%1,%2,%3};"
                 : "+f"(d[0]), "+f"(d[1]), "+f"(d[2]), "+f"(d[3])
                 : "r"(a[0]), "r"(a[1]), "r"(a[2]), "r"(a[3]),
                   "r"(b[0]), "r"(b[1]));
}
__device__ __forceinline__ void cvt_split(float x, unsigned short& hi, unsigned short& lo) {
    __nv_bfloat16 h = __float2bfloat16_rn(x);
    hi = __bfloat16_as_ushort(h);
    lo = __bfloat16_as_ushort(__float2bfloat16_rn(x - __bfloat162float(h)));
}

// ---------------- edge dtype detection ----------------
__global__ void k_detect(const int* __restrict__ ei32) {
    if (threadIdx.x == 0 && blockIdx.x == 0) {
        int zeros = 0;
#pragma unroll
        for (int i = 0; i < 64; i++)
            if (ei32[2 * i + 1] == 0) zeros++;
        d_is64 = (zeros >= 60) ? 1 : 0;
    }
}

__global__ void k_deg_init() {
    int i = blockIdx.x * blockDim.x + threadIdx.x;
    if (i < NNODES) d_degi[i] = 0;
}

__global__ void k_edge_prep(const void* __restrict__ ei) {   // degree over dst
    int e = blockIdx.x * blockDim.x + threadIdx.x;
    if (e >= NEDGES) return;
    int d = d_is64 ? (int)((const long long*)ei)[(size_t)NEDGES + e]
                   : ((const int*)ei)[NEDGES + e];
    atomicAdd(&d_degi[d], 1);
}

__global__ void k_dinv() {
    int i = blockIdx.x * blockDim.x + threadIdx.x;
    if (i < NNODES) d_dinv[i] = rsqrtf((float)(d_degi[i] + 1));
}

// ---------------- W1/W2 -> bf16 hi/lo planes, [k][n] layout ----------------
__global__ void k_wprep(const float* __restrict__ W1, const float* __restrict__ W2) {
    int idx = blockIdx.x * blockDim.x + threadIdx.x;
    if (idx < 256 * 128) {
        unsigned short hi, lo;
        cvt_split(W1[idx], hi, lo);
        d_w1hi[idx] = hi;
        d_w1lo[idx] = lo;
    }
    if (idx < 128 * 64) {
        unsigned short hi, lo;
        cvt_split(W2[idx], hi, lo);
        d_w2hi[idx] = hi;
        d_w2lo[idx] = lo;
    }
}

// ---------------- scan -> rowptr ----------------
__global__ void k_scan1() {
    __shared__ int sh[SCAN_BLK];
    int i = blockIdx.x * SCAN_BLK + threadIdx.x;
    int v = (i < NNODES) ? d_degi[i] : 0;
    sh[threadIdx.x] = v;
    __syncthreads();
    int incl = v;
#pragma unroll
    for (int off = 1; off < SCAN_BLK; off <<= 1) {
        int add = (threadIdx.x >= off) ? sh[threadIdx.x - off] : 0;
        __syncthreads();
        incl += add;
        sh[threadIdx.x] = incl;
        __syncthreads();
    }
    if (i < NNODES) d_rowptr[i] = incl - v;
    if (threadIdx.x == SCAN_BLK - 1) d_bsum[blockIdx.x] = incl;
}
__global__ void k_scan2() {
    __shared__ int sh[SCAN_BLK];
    int t = threadIdx.x;
    int v = (t < SCAN_NB) ? d_bsum[t] : 0;
    sh[t] = v;
    __syncthreads();
    int incl = v;
#pragma unroll
    for (int off = 1; off < SCAN_BLK; off <<= 1) {
        int add = (t >= off) ? sh[t - off] : 0;
        __syncthreads();
        incl += add;
        sh[t] = incl;
        __syncthreads();
    }
    if (t < SCAN_NB) d_boff[t] = incl - v;
}
__global__ void k_scan3() {
    int i = blockIdx.x * blockDim.x + threadIdx.x;
    if (i < NNODES) {
        int r = d_rowptr[i] + d_boff[i / SCAN_BLK];
        d_rowptr[i] = r;
        d_cursor[i] = r;
    }
    if (i == 0) d_rowptr[NNODES] = NEDGES;
}
__global__ void k_csr_fill(const void* __restrict__ ei) {
    int e = blockIdx.x * blockDim.x + threadIdx.x;
    if (e >= NEDGES) return;
    int s, d;
    if (d_is64) {
        const long long* p = (const long long*)ei;
        s = (int)p[e];
        d = (int)p[(size_t)NEDGES + e];
    } else {
        const int* p = (const int*)ei;
        s = p[e];
        d = p[NEDGES + e];
    }
    int pos = atomicAdd(&d_cursor[d], 1);
    d_csr[pos] = s;
}

// ========== GEMM1: mma.sync bf16-split, 128x128 tile, K=256 ==========
// g1h[row] = (fp16) dinv[row]*(latent@W1[0:256] + hist*W1[256] + subg*W1[257])
#define APAD 40
#define BPAD 136
__global__ void __launch_bounds__(256)
k_gemm1_mma(const float* __restrict__ A, const float* __restrict__ W1,
            const float* __restrict__ hist, const float* __restrict__ subg,
            __half* __restrict__ g) {
    __shared__ __align__(16) unsigned short sAh[128][APAD];
    __shared__ __align__(16) unsigned short sAl[128][APAD];
    __shared__ __align__(16) unsigned short sBh[32][BPAD];
    __shared__ __align__(16) unsigned short sBl[32][BPAD];

    const int tid = threadIdx.x;
    const int wid = tid >> 5, lane = tid & 31;
    const int rowBase = blockIdx.x * 128;
    const int mbase = (wid >> 1) * 32;
    const int nbase = (wid & 1) * 64;

    float acc[2][8][4];
#pragma unroll
    for (int i = 0; i < 2; i++)
#pragma unroll
        for (int j = 0; j < 8; j++)
#pragma unroll
            for (int q = 0; q < 4; q++) acc[i][j][q] = 0.f;

    const int aRow = lane & 15, aK = (lane >> 4) * 8;
    const int bK = lane & 15, bN = (lane >> 4) * 8;

    for (int c = 0; c < 8; c++) {
        const int k0 = c * 32;
#pragma unroll
        for (int t = 0; t < 4; t++) {
            int idx = tid + t * 256;
            int m = idx >> 3, f4 = idx & 7;
            int row = rowBase + m;
            float4 v = make_float4(0.f, 0.f, 0.f, 0.f);
            if (row < NNODES)
                v = *(const float4*)(A + (size_t)row * 256 + k0 + f4 * 4);
            unsigned short h0, h1, h2, h3, l0, l1, l2, l3;
            cvt_split(v.x, h0, l0); cvt_split(v.y, h1, l1);
            cvt_split(v.z, h2, l2); cvt_split(v.w, h3, l3);
            uint2 hh, ll;
            hh.x = (uint32_t)h0 | ((uint32_t)h1 << 16);
            hh.y = (uint32_t)h2 | ((uint32_t)h3 << 16);
            ll.x = (uint32_t)l0 | ((uint32_t)l1 << 16);
            ll.y = (uint32_t)l2 | ((uint32_t)l3 << 16);
            *(uint2*)&sAh[m][f4 * 4] = hh;
            *(uint2*)&sAl[m][f4 * 4] = ll;
        }
#pragma unroll
        for (int t = 0; t < 2; t++) {
            int idx = tid + t * 256;
            int k = idx >> 4, u = idx & 15;
            *(uint4*)&sBh[k][u * 8] = *(const uint4*)(d_w1hi + (size_t)(k0 + k) * 128 + u * 8);
            *(uint4*)&sBl[k][u * 8] = *(const uint4*)(d_w1lo + (size_t)(k0 + k) * 128 + u * 8);
        }
        __syncthreads();

#pragma unroll
        for (int ks = 0; ks < 32; ks += 16) {
            uint32_t ah[2][4], al[2][4], bh[4][4], bl[4][4];
#pragma unroll
            for (int mt = 0; mt < 2; mt++) {
                ldmx4(ah[mt], smem_u32(&sAh[mbase + mt * 16 + aRow][ks + aK]));
                ldmx4(al[mt], smem_u32(&sAl[mbase + mt * 16 + aRow][ks + aK]));
            }
#pragma unroll
            for (int ng = 0; ng < 4; ng++) {
                ldmx4t(bh[ng], smem_u32(&sBh[ks + bK][nbase + ng * 16 + bN]));
                ldmx4t(bl[ng], smem_u32(&sBl[ks + bK][nbase + ng * 16 + bN]));
            }
#pragma unroll
            for (int mt = 0; mt < 2; mt++)
#pragma unroll
                for (int ng = 0; ng < 4; ng++) {
                    mma16816(acc[mt][ng * 2 + 0], ah[mt], &bh[ng][0]);
                    mma16816(acc[mt][ng * 2 + 0], ah[mt], &bl[ng][0]);
                    mma16816(acc[mt][ng * 2 + 0], al[mt], &bh[ng][0]);
                    mma16816(acc[mt][ng * 2 + 1], ah[mt], &bh[ng][2]);
                    mma16816(acc[mt][ng * 2 + 1], ah[mt], &bl[ng][2]);
                    mma16816(acc[mt][ng * 2 + 1], al[mt], &bh[ng][2]);
                }
        }
        __syncthreads();
    }

#pragma unroll
    for (int mt = 0; mt < 2; mt++) {
        int r0 = rowBase + mbase + mt * 16 + (lane >> 2);
        int r1 = r0 + 8;
        float dv0 = 0.f, hv0 = 0.f, sv0 = 0.f, dv1 = 0.f, hv1 = 0.f, sv1 = 0.f;
        if (r0 < NNODES) { dv0 = d_dinv[r0]; hv0 = hist[r0]; sv0 = subg[r0]; }
        if (r1 < NNODES) { dv1 = d_dinv[r1]; hv1 = hist[r1]; sv1 = subg[r1]; }
#pragma unroll
        for (int nt = 0; nt < 8; nt++) {
            int col = nbase + nt * 8 + (lane & 3) * 2;
            float w2a = __ldg(&W1[(size_t)256 * 128 + col]);
            float w2b = __ldg(&W1[(size_t)256 * 128 + col + 1]);
            float w3a = __ldg(&W1[(size_t)257 * 128 + col]);
            float w3b = __ldg(&W1[(size_t)257 * 128 + col + 1]);
            if (r0 < NNODES) {
                float ox = (acc[mt][nt][0] + hv0 * w2a + sv0 * w3a) * dv0;
                float oy = (acc[mt][nt][1] + hv0 * w2b + sv0 * w3b) * dv0;
                *(__half2*)(g + (size_t)r0 * 128 + col) = __floats2half2_rn(ox, oy);
            }
            if (r1 < NNODES) {
                float ox = (acc[mt][nt][2] + hv1 * w2a + sv1 * w3a) * dv1;
                float oy = (acc[mt][nt][3] + hv1 * w2b + sv1 * w3b) * dv1;
                *(__half2*)(g + (size_t)r1 * 128 + col) = __floats2half2_rn(ox, oy);
            }
        }
    }
}

// -------- gather1: fp16 source, F=128, GROUP=16 lanes/node -----------------
__global__ void k_gather_h(const __half* __restrict__ g, float* __restrict__ o) {
    const int lane = threadIdx.x & 31;
    const int warp = (blockIdx.x * blockDim.x + threadIdx.x) >> 5;
    const int gid  = lane >> 4;          // 0..1
    const int sub  = lane & 15;          // owns cols sub*8..sub*8+7
    const int base = gid * 16;
    const int node = warp * 2 + gid;
    const bool valid = node < NNODES;

    int beg = valid ? __ldg(&d_rowptr[node])     : 0;
    int end = valid ? __ldg(&d_rowptr[node + 1]) : 0;
    int len = end - beg;

    float acc[8];
#pragma unroll
    for (int j = 0; j < 8; j++) acc[j] = 0.f;

    auto addRow = [&](int ss) {
        uint4 q = __ldg((const uint4*)(g + (size_t)ss * 128) + sub);
        float2 f0 = __half22float2(*(__half2*)&q.x);
        float2 f1 = __half22float2(*(__half2*)&q.y);
        float2 f2 = __half22float2(*(__half2*)&q.z);
        float2 f3 = __half22float2(*(__half2*)&q.w);
        acc[0] += f0.x; acc[1] += f0.y; acc[2] += f1.x; acc[3] += f1.y;
        acc[4] += f2.x; acc[5] += f2.y; acc[6] += f3.x; acc[7] += f3.y;
    };
    if (valid) addRow(node);             // self-loop

    int maxlen = len;
#pragma unroll
    for (int off = 16; off; off >>= 1)
        maxlen = max(maxlen, __shfl_xor_sync(0xffffffffu, maxlen, off));

    int s_pre = 0;
    for (int t = 0; t < maxlen; t++) {
        if ((t & 15) == 0) {
            int j = beg + t + sub;
            s_pre = (j < end) ? __ldg(&d_csr[j]) : 0;
        }
        int ss = __shfl_sync(0xffffffffu, s_pre, base + (t & 15));
        if (t < len) addRow(ss);
    }
    if (valid) {
        float4 o0 = make_float4(acc[0], acc[1], acc[2], acc[3]);
        float4 o1 = make_float4(acc[4], acc[5], acc[6], acc[7]);
        *(float4*)(o + (size_t)node * 128 + sub * 8) = o0;
        *(float4*)(o + (size_t)node * 128 + sub * 8 + 4) = o1;
    }
}

// ========== GEMM2: mma.sync bf16-split, 128x64 tile, K=128 ==========
// g2[row] = dinv[row] * (relu(dinv*o1+b1) @ W2)
#define BPAD2 72
__global__ void __launch_bounds__(256)
k_gemm2_mma(const float* __restrict__ A, const float* __restrict__ b1,
            float* __restrict__ g) {
    __shared__ __align__(16) unsigned short sAh[128][APAD];
    __shared__ __align__(16) unsigned short sAl[128][APAD];
    __shared__ __align__(16) unsigned short sBh[32][BPAD2];
    __shared__ __align__(16) unsigned short sBl[32][BPAD2];

    const int tid = threadIdx.x;
    const int wid = tid >> 5, lane = tid & 31;
    const int rowBase = blockIdx.x * 128;
    const int mbase = wid * 16;

    float acc[8][4];
#pragma unroll
    for (int j = 0; j < 8; j++)
#pragma unroll
        for (int q = 0; q < 4; q++) acc[j][q] = 0.f;

    const int aRow = lane & 15, aK = (lane >> 4) * 8;
    const int bK = lane & 15, bN = (lane >> 4) * 8;

    for (int c = 0; c < 4; c++) {
        const int k0 = c * 32;
#pragma unroll
        for (int t = 0; t < 4; t++) {
            int idx = tid + t * 256;
            int m = idx >> 3, f4 = idx & 7;
            int row = rowBase + m;
            float4 v = make_float4(0.f, 0.f, 0.f, 0.f);
            if (row < NNODES) {
                v = *(const float4*)(A + (size_t)row * 128 + k0 + f4 * 4);
                float dv = d_dinv[row];
                int kk = k0 + f4 * 4;
                v.x = fmaxf(fmaf(dv, v.x, __ldg(&b1[kk + 0])), 0.f);
                v.y = fmaxf(fmaf(dv, v.y, __ldg(&b1[kk + 1])), 0.f);
                v.z = fmaxf(fmaf(dv, v.z, __ldg(&b1[kk + 2])), 0.f);
                v.w = fmaxf(fmaf(dv, v.w, __ldg(&b1[kk + 3])), 0.f);
            }
            unsigned short h0, h1, h2, h3, l0, l1, l2, l3;
            cvt_split(v.x, h0, l0); cvt_split(v.y, h1, l1);
            cvt_split(v.z, h2, l2); cvt_split(v.w, h3, l3);
            uint2 hh, ll;
            hh.x = (uint32_t)h0 | ((uint32_t)h1 << 16);
            hh.y = (uint32_t)h2 | ((uint32_t)h3 << 16);
            ll.x = (uint32_t)l0 | ((uint32_t)l1 << 16);
            ll.y = (uint32_t)l2 | ((uint32_t)l3 << 16);
            *(uint2*)&sAh[m][f4 * 4] = hh;
            *(uint2*)&sAl[m][f4 * 4] = ll;
        }
        // B: 32 k-rows x 64 n = 8 uint4/row -> 256 uint4 per plane
        {
            int k = tid >> 3, u = tid & 7;
            *(uint4*)&sBh[k][u * 8] = *(const uint4*)(d_w2hi + (size_t)(k0 + k) * 64 + u * 8);
            *(uint4*)&sBl[k][u * 8] = *(const uint4*)(d_w2lo + (size_t)(k0 + k) * 64 + u * 8);
        }
        __syncthreads();

#pragma unroll
        for (int ks = 0; ks < 32; ks += 16) {
            uint32_t ah[4], al[4], bh[4][4], bl[4][4];
            ldmx4(ah, smem_u32(&sAh[mbase + aRow][ks + aK]));
            ldmx4(al, smem_u32(&sAl[mbase + aRow][ks + aK]));
#pragma unroll
            for (int ng = 0; ng < 4; ng++) {
                ldmx4t(bh[ng], smem_u32(&sBh[ks + bK][ng * 16 + bN]));
                ldmx4t(bl[ng], smem_u32(&sBl[ks + bK][ng * 16 + bN]));
            }
#pragma unroll
            for (int ng = 0; ng < 4; ng++) {
                mma16816(acc[ng * 2 + 0], ah, &bh[ng][0]);
                mma16816(acc[ng * 2 + 0], ah, &bl[ng][0]);
                mma16816(acc[ng * 2 + 0], al, &bh[ng][0]);
                mma16816(acc[ng * 2 + 1], ah, &bh[ng][2]);
                mma16816(acc[ng * 2 + 1], ah, &bl[ng][2]);
                mma16816(acc[ng * 2 + 1], al, &bh[ng][2]);
            }
        }
        __syncthreads();
    }

    int r0 = rowBase + mbase + (lane >> 2);
    int r1 = r0 + 8;
    float dv0 = (r0 < NNODES) ? d_dinv[r0] : 0.f;
    float dv1 = (r1 < NNODES) ? d_dinv[r1] : 0.f;
#pragma unroll
    for (int nt = 0; nt < 8; nt++) {
        int col = nt * 8 + (lane & 3) * 2;
        if (r0 < NNODES) {
            float2 o = make_float2(acc[nt][0] * dv0, acc[nt][1] * dv0);
            *(float2*)(g + (size_t)r0 * 64 + col) = o;
        }
        if (r1 < NNODES) {
            float2 o = make_float2(acc[nt][2] * dv1, acc[nt][3] * dv1);
            *(float2*)(g + (size_t)r1 * 64 + col) = o;
        }
    }
}

// ------------- CSR pull-gather (fp32 source) ----------
template<int F, int GROUP>
__global__ void k_gather(const float* __restrict__ g, float* __restrict__ o) {
    const int lane = threadIdx.x & 31;
    const int warp = (blockIdx.x * blockDim.x + threadIdx.x) >> 5;
    constexpr int NPW = 32 / GROUP;
    const int gid  = lane / GROUP;
    const int sub  = lane % GROUP;
    const int base = gid * GROUP;
    const int node = warp * NPW + gid;
    const bool valid = node < NNODES;

    int beg = valid ? __ldg(&d_rowptr[node])     : 0;
    int end = valid ? __ldg(&d_rowptr[node + 1]) : 0;
    int len = end - beg;

    float4 acc = make_float4(0.f, 0.f, 0.f, 0.f);
    if (valid)
        acc = __ldg((const float4*)(g + (size_t)node * F) + sub);

    int maxlen = len;
#pragma unroll
    for (int off = 16; off; off >>= 1)
        maxlen = max(maxlen, __shfl_xor_sync(0xffffffffu, maxlen, off));

    int s_pre = 0;
    for (int t = 0; t < maxlen; t++) {
        if ((t % GROUP) == 0) {
            int j = beg + t + sub;
            s_pre = (j < end) ? __ldg(&d_csr[j]) : 0;
        }
        int ss = __shfl_sync(0xffffffffu, s_pre, base + (t % GROUP));
        if (t < len) {
            float4 v = __ldg((const float4*)(g + (size_t)ss * F) + sub);
            acc.x += v.x; acc.y += v.y; acc.z += v.z; acc.w += v.w;
        }
    }
    if (valid)
        *((float4*)(o + (size_t)node * F) + sub) = acc;
}

// ------- layer 3 GEMM ------
__global__ void __launch_bounds__(256) k_gemm3(const float* __restrict__ W3,
                                               const float* __restrict__ b2) {
    __shared__ float Ws[64 * 8];
    __shared__ float Bb[64];
    __shared__ __align__(16) float Hs[32][65];
    int tid = threadIdx.x;
    for (int i = tid; i < 512; i += 256) Ws[i] = W3[i];
    if (tid < 64) Bb[tid] = b2[tid];
    int nodeBase = blockIdx.x * 32;
    __syncthreads();
    for (int i = tid; i < 512; i += 256) {
        int r = i / 16, c4 = i % 16;
        int node = nodeBase + r;
        if (node < NNODES) {
            float dv = d_dinv[node];
            float4 v = *(const float4*)(d_o2 + (size_t)node * 64 + c4 * 4);
            Hs[r][c4 * 4 + 0] = fmaxf(fmaf(dv, v.x, Bb[c4 * 4 + 0]), 0.f);
            Hs[r][c4 * 4 + 1] = fmaxf(fmaf(dv, v.y, Bb[c4 * 4 + 1]), 0.f);
            Hs[r][c4 * 4 + 2] = fmaxf(fmaf(dv, v.z, Bb[c4 * 4 + 2]), 0.f);
            Hs[r][c4 * 4 + 3] = fmaxf(fmaf(dv, v.w, Bb[c4 * 4 + 3]), 0.f);
        }
    }
    __syncthreads();
    int ln = tid / 8, col = tid % 8;
    int node = nodeBase + ln;
    if (node >= NNODES) return;
    float acc = 0.f;
#pragma unroll
    for (int k = 0; k < 64; k++) acc = fmaf(Hs[ln][k], Ws[k * 8 + col], acc);
    d_g3[(size_t)node * 8 + col] = d_dinv[node] * acc;
}

// ---------------- final head ----------------
__global__ void k_head(const float* __restrict__ Wc, const float* __restrict__ bc,
                       const float* __restrict__ b3, float* __restrict__ out) {
    int n = blockIdx.x * blockDim.x + threadIdx.x;
    if (n >= NNODES) return;
    float dv = d_dinv[n];
    float4 p0 = *(const float4*)(d_o3 + (size_t)n * 8);
    float4 p1 = *(const float4*)(d_o3 + (size_t)n * 8 + 4);
    float h[8] = {p0.x, p0.y, p0.z, p0.w, p1.x, p1.y, p1.z, p1.w};
    float r0 = __ldg(&bc[0]), r1 = __ldg(&bc[1]), r2 = __ldg(&bc[2]);
#pragma unroll
    for (int j = 0; j < 8; j++) {
        float hv = fmaxf(fmaf(dv, h[j], __ldg(&b3[j])), 0.f);
        r0 = fmaf(hv, __ldg(&Wc[j * 3 + 0]), r0);
        r1 = fmaf(hv, __ldg(&Wc[j * 3 + 1]), r1);
        r2 = fmaf(hv, __ldg(&Wc[j * 3 + 2]), r2);
    }
    out[(size_t)n * 3 + 0] = r0;
    out[(size_t)n * 3 + 1] = r1;
    out[(size_t)n * 3 + 2] = r2;
}

// ---------------- launch ----------------
extern "C" void kernel_launch(void* const* d_in, const int* in_sizes, int n_in,
                              void* d_out, int out_size) {
    const float* latent = (const float*)d_in[0];
    const float* hist   = (const float*)d_in[1];
    const float* subg   = (const float*)d_in[2];
    const void*  ei     = d_in[3];
    const float* W1 = (const float*)d_in[4];
    const float* b1 = (const float*)d_in[5];
    const float* W2 = (const float*)d_in[6];
    const float* b2 = (const float*)d_in[7];
    const float* W3 = (const float*)d_in[8];
    const float* b3 = (const float*)d_in[9];
    const float* Wc = (const float*)d_in[10];
    const float* bc = (const float*)d_in[11];
    float* out = (float*)d_out;

    __half* g1h;
    float *o1, *g2, *o2, *g3, *o3;
    cudaGetSymbolAddress((void**)&g1h, d_g1h);
    cudaGetSymbolAddress((void**)&o1, d_o1);
    cudaGetSymbolAddress((void**)&g2, d_g2);
    cudaGetSymbolAddress((void**)&o2, d_o2);
    cudaGetSymbolAddress((void**)&g3, d_g3);
    cudaGetSymbolAddress((void**)&o3, d_o3);

    k_detect<<<1, 32>>>((const int*)ei);
    k_deg_init<<<(NNODES + 255) / 256, 256>>>();
    k_edge_prep<<<(NEDGES + 255) / 256, 256>>>(ei);
    k_dinv<<<(NNODES + 255) / 256, 256>>>();
    k_wprep<<<(256 * 128 + 255) / 256, 256>>>(W1, W2);

    // GEMM1 on tensor cores (mma.sync bf16-split), fp16 output
    k_gemm1_mma<<<(NNODES + 127) / 128, 256>>>(latent, W1, hist, subg, g1h);

    // CSR build
    k_scan1<<<SCAN_NB, SCAN_BLK>>>();
    k_scan2<<<1, SCAN_BLK>>>();
    k_scan3<<<(NNODES + 255) / 256, 256>>>();
    k_csr_fill<<<(NEDGES + 255) / 256, 256>>>(ei);

    // layer 1 aggregate (fp16 source, fp32 accumulate)
    k_gather_h<<<(NNODES * 16 + 255) / 256, 256>>>(g1h, o1);

    // layer 2 on tensor cores, fused relu(dinv*o1+b1)
    k_gemm2_mma<<<(NNODES + 127) / 128, 256>>>(o1, b1, g2);
    k_gather<64, 16><<<(NNODES * 16 + 255) / 256, 256>>>(g2, o2);

    // layer 3: 64 -> 8
    k_gemm3<<<(NNODES + 31) / 32, 256>>>(W3, b2);
    k_gather<8, 2><<<(NNODES * 2 + 255) / 256, 256>>>(g3, o3);

    k_head<<<(NNODES + 255) / 256, 256>>>(Wc, bc, b3, out);
}

// round 9
// speedup vs baseline: 2.4058x; 1.0540x over previous
#include <cuda_runtime.h>
#include <cuda_bf16.h>
#include <cuda_fp16.h>
#include <math.h>
#include <stdint.h>

#define NNODES 200000
#define NEDGES 3200000
#define SCAN_BLK 512
#define SCAN_NB ((NNODES + SCAN_BLK - 1) / SCAN_BLK)   // 391

// ---------------- scratch (no allocations allowed) ----------------
__device__ __align__(256) int   d_degi[NNODES];
__device__ __align__(256) float d_dinv[NNODES];
__device__ __align__(256) int   d_csr[NEDGES];
__device__ __align__(256) int   d_rowptr[NNODES + 1];
__device__ __align__(256) int   d_cursor[NNODES];
__device__ __align__(256) int   d_bsum[SCAN_NB];
__device__ __align__(256) int   d_boff[SCAN_NB];
__device__ __align__(256) unsigned short d_w1hi[256 * 128];  // [k][n] bf16
__device__ __align__(256) unsigned short d_w1lo[256 * 128];
__device__ __align__(256) unsigned short d_w2hi[128 * 64];   // [k][n] bf16
__device__ __align__(256) unsigned short d_w2lo[128 * 64];
__device__ __align__(256) __half d_g1h[(size_t)NNODES * 128];
__device__ __align__(256) float d_o1[(size_t)NNODES * 128];
__device__ __align__(256) __half d_g2h[(size_t)NNODES * 64];
__device__ __align__(256) float d_o2[(size_t)NNODES * 64];
__device__ __align__(256) float d_g3[(size_t)NNODES * 8];
__device__ __align__(256) float d_o3[(size_t)NNODES * 8];
__device__ int d_is64;

// ---------------- PTX helpers (baseline ISA only, sm_103-safe) -------------
__device__ __forceinline__ uint32_t smem_u32(const void* p) {
    uint32_t a;
    asm("{ .reg .u64 t; cvta.to.shared.u64 t, %1; cvt.u32.u64 %0, t; }"
        : "=r"(a) : "l"(p));
    return a;
}
__device__ __forceinline__ void ldmx4(uint32_t* r, uint32_t addr) {
    asm volatile("ldmatrix.sync.aligned.m8n8.x4.shared.b16 {%0,%1,%2,%3}, [%4];"
                 : "=r"(r[0]), "=r"(r[1]), "=r"(r[2]), "=r"(r[3]) : "r"(addr));
}
__device__ __forceinline__ void ldmx4t(uint32_t* r, uint32_t addr) {
    asm volatile("ldmatrix.sync.aligned.m8n8.x4.trans.shared.b16 {%0,%1,%2,%3}, [%4];"
                 : "=r"(r[0]), "=r"(r[1]), "=r"(r[2]), "=r"(r[3]) : "r"(addr));
}
__device__ __forceinline__ void mma16816(float* d, const uint32_t* a, const uint32_t* b) {
    asm volatile("mma.sync.aligned.m16n8k16.row.col.f32.bf16.bf16.f32 "
                 "{%0,%1,%2,%3}, {%4,%5,%6,%7}, {%8,%9}, {%0,%1,%2,%3};"
                 : "+f"(d[0]), "+f"(d[1]), "+f"(d[2]), "+f"(d[3])
                 : "r"(a[0]), "r"(a[1]), "r"(a[2]), "r"(a[3]),
                   "r"(b[0]), "r"(b[1]));
}
__device__ __forceinline__ void cvt_split(float x, unsigned short& hi, unsigned short& lo) {
    __nv_bfloat16 h = __float2bfloat16_rn(x);
    hi = __bfloat16_as_ushort(h);
    lo = __bfloat16_as_ushort(__float2bfloat16_rn(x - __bfloat162float(h)));
}

// ---------------- edge dtype detection ----------------
__global__ void k_detect(const int* __restrict__ ei32) {
    if (threadIdx.x == 0 && blockIdx.x == 0) {
        int zeros = 0;
#pragma unroll
        for (int i = 0; i < 64; i++)
            if (ei32[2 * i + 1] == 0) zeros++;
        d_is64 = (zeros >= 60) ? 1 : 0;
    }
}

__global__ void k_deg_init() {
    int i = blockIdx.x * blockDim.x + threadIdx.x;
    if (i < NNODES) d_degi[i] = 0;
}

__global__ void k_edge_prep(const void* __restrict__ ei) {   // degree over dst
    int e = blockIdx.x * blockDim.x + threadIdx.x;
    if (e >= NEDGES) return;
    int d = d_is64 ? (int)((const long long*)ei)[(size_t)NEDGES + e]
                   : ((const int*)ei)[NEDGES + e];
    atomicAdd(&d_degi[d], 1);
}

__global__ void k_dinv() {
    int i = blockIdx.x * blockDim.x + threadIdx.x;
    if (i < NNODES) d_dinv[i] = rsqrtf((float)(d_degi[i] + 1));
}

// ---------------- W1/W2 -> bf16 hi/lo planes, [k][n] layout ----------------
__global__ void k_wprep(const float* __restrict__ W1, const float* __restrict__ W2) {
    int idx = blockIdx.x * blockDim.x + threadIdx.x;
    if (idx < 256 * 128) {
        unsigned short hi, lo;
        cvt_split(W1[idx], hi, lo);
        d_w1hi[idx] = hi;
        d_w1lo[idx] = lo;
    }
    if (idx < 128 * 64) {
        unsigned short hi, lo;
        cvt_split(W2[idx], hi, lo);
        d_w2hi[idx] = hi;
        d_w2lo[idx] = lo;
    }
}

// ---------------- scan -> rowptr ----------------
__global__ void k_scan1() {
    __shared__ int sh[SCAN_BLK];
    int i = blockIdx.x * SCAN_BLK + threadIdx.x;
    int v = (i < NNODES) ? d_degi[i] : 0;
    sh[threadIdx.x] = v;
    __syncthreads();
    int incl = v;
#pragma unroll
    for (int off = 1; off < SCAN_BLK; off <<= 1) {
        int add = (threadIdx.x >= off) ? sh[threadIdx.x - off] : 0;
        __syncthreads();
        incl += add;
        sh[threadIdx.x] = incl;
        __syncthreads();
    }
    if (i < NNODES) d_rowptr[i] = incl - v;
    if (threadIdx.x == SCAN_BLK - 1) d_bsum[blockIdx.x] = incl;
}
__global__ void k_scan2() {
    __shared__ int sh[SCAN_BLK];
    int t = threadIdx.x;
    int v = (t < SCAN_NB) ? d_bsum[t] : 0;
    sh[t] = v;
    __syncthreads();
    int incl = v;
#pragma unroll
    for (int off = 1; off < SCAN_BLK; off <<= 1) {
        int add = (t >= off) ? sh[t - off] : 0;
        __syncthreads();
        incl += add;
        sh[t] = incl;
        __syncthreads();
    }
    if (t < SCAN_NB) d_boff[t] = incl - v;
}
__global__ void k_scan3() {
    int i = blockIdx.x * blockDim.x + threadIdx.x;
    if (i < NNODES) {
        int r = d_rowptr[i] + d_boff[i / SCAN_BLK];
        d_rowptr[i] = r;
        d_cursor[i] = r;
    }
    if (i == 0) d_rowptr[NNODES] = NEDGES;
}
__global__ void k_csr_fill(const void* __restrict__ ei) {
    int e = blockIdx.x * blockDim.x + threadIdx.x;
    if (e >= NEDGES) return;
    int s, d;
    if (d_is64) {
        const long long* p = (const long long*)ei;
        s = (int)p[e];
        d = (int)p[(size_t)NEDGES + e];
    } else {
        const int* p = (const int*)ei;
        s = p[e];
        d = p[NEDGES + e];
    }
    int pos = atomicAdd(&d_cursor[d], 1);
    d_csr[pos] = s;
}

// ========== GEMM1: mma.sync bf16-split, 128x128 tile, K=256 ==========
// g1h[row] = (fp16) dinv[row]*(latent@W1[0:256] + hist*W1[256] + subg*W1[257])
#define APAD 40
#define BPAD 136
__global__ void __launch_bounds__(256)
k_gemm1_mma(const float* __restrict__ A, const float* __restrict__ W1,
            const float* __restrict__ hist, const float* __restrict__ subg,
            __half* __restrict__ g) {
    __shared__ __align__(16) unsigned short sAh[128][APAD];
    __shared__ __align__(16) unsigned short sAl[128][APAD];
    __shared__ __align__(16) unsigned short sBh[32][BPAD];
    __shared__ __align__(16) unsigned short sBl[32][BPAD];

    const int tid = threadIdx.x;
    const int wid = tid >> 5, lane = tid & 31;
    const int rowBase = blockIdx.x * 128;
    const int mbase = (wid >> 1) * 32;
    const int nbase = (wid & 1) * 64;

    float acc[2][8][4];
#pragma unroll
    for (int i = 0; i < 2; i++)
#pragma unroll
        for (int j = 0; j < 8; j++)
#pragma unroll
            for (int q = 0; q < 4; q++) acc[i][j][q] = 0.f;

    const int aRow = lane & 15, aK = (lane >> 4) * 8;
    const int bK = lane & 15, bN = (lane >> 4) * 8;

    for (int c = 0; c < 8; c++) {
        const int k0 = c * 32;
#pragma unroll
        for (int t = 0; t < 4; t++) {
            int idx = tid + t * 256;
            int m = idx >> 3, f4 = idx & 7;
            int row = rowBase + m;
            float4 v = make_float4(0.f, 0.f, 0.f, 0.f);
            if (row < NNODES)
                v = *(const float4*)(A + (size_t)row * 256 + k0 + f4 * 4);
            unsigned short h0, h1, h2, h3, l0, l1, l2, l3;
            cvt_split(v.x, h0, l0); cvt_split(v.y, h1, l1);
            cvt_split(v.z, h2, l2); cvt_split(v.w, h3, l3);
            uint2 hh, ll;
            hh.x = (uint32_t)h0 | ((uint32_t)h1 << 16);
            hh.y = (uint32_t)h2 | ((uint32_t)h3 << 16);
            ll.x = (uint32_t)l0 | ((uint32_t)l1 << 16);
            ll.y = (uint32_t)l2 | ((uint32_t)l3 << 16);
            *(uint2*)&sAh[m][f4 * 4] = hh;
            *(uint2*)&sAl[m][f4 * 4] = ll;
        }
#pragma unroll
        for (int t = 0; t < 2; t++) {
            int idx = tid + t * 256;
            int k = idx >> 4, u = idx & 15;
            *(uint4*)&sBh[k][u * 8] = *(const uint4*)(d_w1hi + (size_t)(k0 + k) * 128 + u * 8);
            *(uint4*)&sBl[k][u * 8] = *(const uint4*)(d_w1lo + (size_t)(k0 + k) * 128 + u * 8);
        }
        __syncthreads();

#pragma unroll
        for (int ks = 0; ks < 32; ks += 16) {
            uint32_t ah[2][4], al[2][4], bh[4][4], bl[4][4];
#pragma unroll
            for (int mt = 0; mt < 2; mt++) {
                ldmx4(ah[mt], smem_u32(&sAh[mbase + mt * 16 + aRow][ks + aK]));
                ldmx4(al[mt], smem_u32(&sAl[mbase + mt * 16 + aRow][ks + aK]));
            }
#pragma unroll
            for (int ng = 0; ng < 4; ng++) {
                ldmx4t(bh[ng], smem_u32(&sBh[ks + bK][nbase + ng * 16 + bN]));
                ldmx4t(bl[ng], smem_u32(&sBl[ks + bK][nbase + ng * 16 + bN]));
            }
#pragma unroll
            for (int mt = 0; mt < 2; mt++)
#pragma unroll
                for (int ng = 0; ng < 4; ng++) {
                    mma16816(acc[mt][ng * 2 + 0], ah[mt], &bh[ng][0]);
                    mma16816(acc[mt][ng * 2 + 0], ah[mt], &bl[ng][0]);
                    mma16816(acc[mt][ng * 2 + 0], al[mt], &bh[ng][0]);
                    mma16816(acc[mt][ng * 2 + 1], ah[mt], &bh[ng][2]);
                    mma16816(acc[mt][ng * 2 + 1], ah[mt], &bl[ng][2]);
                    mma16816(acc[mt][ng * 2 + 1], al[mt], &bh[ng][2]);
                }
        }
        __syncthreads();
    }

#pragma unroll
    for (int mt = 0; mt < 2; mt++) {
        int r0 = rowBase + mbase + mt * 16 + (lane >> 2);
        int r1 = r0 + 8;
        float dv0 = 0.f, hv0 = 0.f, sv0 = 0.f, dv1 = 0.f, hv1 = 0.f, sv1 = 0.f;
        if (r0 < NNODES) { dv0 = d_dinv[r0]; hv0 = hist[r0]; sv0 = subg[r0]; }
        if (r1 < NNODES) { dv1 = d_dinv[r1]; hv1 = hist[r1]; sv1 = subg[r1]; }
#pragma unroll
        for (int nt = 0; nt < 8; nt++) {
            int col = nbase + nt * 8 + (lane & 3) * 2;
            float w2a = __ldg(&W1[(size_t)256 * 128 + col]);
            float w2b = __ldg(&W1[(size_t)256 * 128 + col + 1]);
            float w3a = __ldg(&W1[(size_t)257 * 128 + col]);
            float w3b = __ldg(&W1[(size_t)257 * 128 + col + 1]);
            if (r0 < NNODES) {
                float ox = (acc[mt][nt][0] + hv0 * w2a + sv0 * w3a) * dv0;
                float oy = (acc[mt][nt][1] + hv0 * w2b + sv0 * w3b) * dv0;
                *(__half2*)(g + (size_t)r0 * 128 + col) = __floats2half2_rn(ox, oy);
            }
            if (r1 < NNODES) {
                float ox = (acc[mt][nt][2] + hv1 * w2a + sv1 * w3a) * dv1;
                float oy = (acc[mt][nt][3] + hv1 * w2b + sv1 * w3b) * dv1;
                *(__half2*)(g + (size_t)r1 * 128 + col) = __floats2half2_rn(ox, oy);
            }
        }
    }
}

// -------- fp16 pull-gather: F halves/row, GROUP=F/8 lanes/node -------------
template<int F, int GROUP>
__global__ void k_gather_h(const __half* __restrict__ g, float* __restrict__ o) {
    const int lane = threadIdx.x & 31;
    const int warp = (blockIdx.x * blockDim.x + threadIdx.x) >> 5;
    constexpr int NPW = 32 / GROUP;
    const int gid  = lane / GROUP;
    const int sub  = lane % GROUP;          // owns halves sub*8..sub*8+7
    const int base = gid * GROUP;
    const int node = warp * NPW + gid;
    const bool valid = node < NNODES;

    int beg = valid ? __ldg(&d_rowptr[node])     : 0;
    int end = valid ? __ldg(&d_rowptr[node + 1]) : 0;
    int len = end - beg;

    float acc[8];
#pragma unroll
    for (int j = 0; j < 8; j++) acc[j] = 0.f;

    auto addRow = [&](int ss) {
        uint4 q = __ldg((const uint4*)(g + (size_t)ss * F) + sub);
        float2 f0 = __half22float2(*(__half2*)&q.x);
        float2 f1 = __half22float2(*(__half2*)&q.y);
        float2 f2 = __half22float2(*(__half2*)&q.z);
        float2 f3 = __half22float2(*(__half2*)&q.w);
        acc[0] += f0.x; acc[1] += f0.y; acc[2] += f1.x; acc[3] += f1.y;
        acc[4] += f2.x; acc[5] += f2.y; acc[6] += f3.x; acc[7] += f3.y;
    };
    if (valid) addRow(node);             // self-loop

    int maxlen = len;
#pragma unroll
    for (int off = 16; off; off >>= 1)
        maxlen = max(maxlen, __shfl_xor_sync(0xffffffffu, maxlen, off));

    int s_pre = 0;
    for (int t = 0; t < maxlen; t++) {
        if ((t % GROUP) == 0) {
            int j = beg + t + sub;
            s_pre = (j < end) ? __ldg(&d_csr[j]) : 0;
        }
        int ss = __shfl_sync(0xffffffffu, s_pre, base + (t % GROUP));
        if (t < len) addRow(ss);
    }
    if (valid) {
        float4 o0 = make_float4(acc[0], acc[1], acc[2], acc[3]);
        float4 o1 = make_float4(acc[4], acc[5], acc[6], acc[7]);
        *(float4*)(o + (size_t)node * F + sub * 8) = o0;
        *(float4*)(o + (size_t)node * F + sub * 8 + 4) = o1;
    }
}

// ========== GEMM2: mma.sync bf16-split, 128x64 tile, K=128 ==========
// g2h[row] = (fp16) dinv[row] * (relu(dinv*o1+b1) @ W2)
#define BPAD2 72
__global__ void __launch_bounds__(256)
k_gemm2_mma(const float* __restrict__ A, const float* __restrict__ b1,
            __half* __restrict__ g) {
    __shared__ __align__(16) unsigned short sAh[128][APAD];
    __shared__ __align__(16) unsigned short sAl[128][APAD];
    __shared__ __align__(16) unsigned short sBh[32][BPAD2];
    __shared__ __align__(16) unsigned short sBl[32][BPAD2];

    const int tid = threadIdx.x;
    const int wid = tid >> 5, lane = tid & 31;
    const int rowBase = blockIdx.x * 128;
    const int mbase = wid * 16;

    float acc[8][4];
#pragma unroll
    for (int j = 0; j < 8; j++)
#pragma unroll
        for (int q = 0; q < 4; q++) acc[j][q] = 0.f;

    const int aRow = lane & 15, aK = (lane >> 4) * 8;
    const int bK = lane & 15, bN = (lane >> 4) * 8;

    for (int c = 0; c < 4; c++) {
        const int k0 = c * 32;
#pragma unroll
        for (int t = 0; t < 4; t++) {
            int idx = tid + t * 256;
            int m = idx >> 3, f4 = idx & 7;
            int row = rowBase + m;
            float4 v = make_float4(0.f, 0.f, 0.f, 0.f);
            if (row < NNODES) {
                v = *(const float4*)(A + (size_t)row * 128 + k0 + f4 * 4);
                float dv = d_dinv[row];
                int kk = k0 + f4 * 4;
                v.x = fmaxf(fmaf(dv, v.x, __ldg(&b1[kk + 0])), 0.f);
                v.y = fmaxf(fmaf(dv, v.y, __ldg(&b1[kk + 1])), 0.f);
                v.z = fmaxf(fmaf(dv, v.z, __ldg(&b1[kk + 2])), 0.f);
                v.w = fmaxf(fmaf(dv, v.w, __ldg(&b1[kk + 3])), 0.f);
            }
            unsigned short h0, h1, h2, h3, l0, l1, l2, l3;
            cvt_split(v.x, h0, l0); cvt_split(v.y, h1, l1);
            cvt_split(v.z, h2, l2); cvt_split(v.w, h3, l3);
            uint2 hh, ll;
            hh.x = (uint32_t)h0 | ((uint32_t)h1 << 16);
            hh.y = (uint32_t)h2 | ((uint32_t)h3 << 16);
            ll.x = (uint32_t)l0 | ((uint32_t)l1 << 16);
            ll.y = (uint32_t)l2 | ((uint32_t)l3 << 16);
            *(uint2*)&sAh[m][f4 * 4] = hh;
            *(uint2*)&sAl[m][f4 * 4] = ll;
        }
        {
            int k = tid >> 3, u = tid & 7;
            *(uint4*)&sBh[k][u * 8] = *(const uint4*)(d_w2hi + (size_t)(k0 + k) * 64 + u * 8);
            *(uint4*)&sBl[k][u * 8] = *(const uint4*)(d_w2lo + (size_t)(k0 + k) * 64 + u * 8);
        }
        __syncthreads();

#pragma unroll
        for (int ks = 0; ks < 32; ks += 16) {
            uint32_t ah[4], al[4], bh[4][4], bl[4][4];
            ldmx4(ah, smem_u32(&sAh[mbase + aRow][ks + aK]));
            ldmx4(al, smem_u32(&sAl[mbase + aRow][ks + aK]));
#pragma unroll
            for (int ng = 0; ng < 4; ng++) {
                ldmx4t(bh[ng], smem_u32(&sBh[ks + bK][ng * 16 + bN]));
                ldmx4t(bl[ng], smem_u32(&sBl[ks + bK][ng * 16 + bN]));
            }
#pragma unroll
            for (int ng = 0; ng < 4; ng++) {
                mma16816(acc[ng * 2 + 0], ah, &bh[ng][0]);
                mma16816(acc[ng * 2 + 0], ah, &bl[ng][0]);
                mma16816(acc[ng * 2 + 0], al, &bh[ng][0]);
                mma16816(acc[ng * 2 + 1], ah, &bh[ng][2]);
                mma16816(acc[ng * 2 + 1], ah, &bl[ng][2]);
                mma16816(acc[ng * 2 + 1], al, &bh[ng][2]);
            }
        }
        __syncthreads();
    }

    int r0 = rowBase + mbase + (lane >> 2);
    int r1 = r0 + 8;
    float dv0 = (r0 < NNODES) ? d_dinv[r0] : 0.f;
    float dv1 = (r1 < NNODES) ? d_dinv[r1] : 0.f;
#pragma unroll
    for (int nt = 0; nt < 8; nt++) {
        int col = nt * 8 + (lane & 3) * 2;
        if (r0 < NNODES)
            *(__half2*)(g + (size_t)r0 * 64 + col) =
                __floats2half2_rn(acc[nt][0] * dv0, acc[nt][1] * dv0);
        if (r1 < NNODES)
            *(__half2*)(g + (size_t)r1 * 64 + col) =
                __floats2half2_rn(acc[nt][2] * dv1, acc[nt][3] * dv1);
    }
}

// ------------- CSR pull-gather (fp32 source, layer 3) ----------
template<int F, int GROUP>
__global__ void k_gather(const float* __restrict__ g, float* __restrict__ o) {
    const int lane = threadIdx.x & 31;
    const int warp = (blockIdx.x * blockDim.x + threadIdx.x) >> 5;
    constexpr int NPW = 32 / GROUP;
    const int gid  = lane / GROUP;
    const int sub  = lane % GROUP;
    const int base = gid * GROUP;
    const int node = warp * NPW + gid;
    const bool valid = node < NNODES;

    int beg = valid ? __ldg(&d_rowptr[node])     : 0;
    int end = valid ? __ldg(&d_rowptr[node + 1]) : 0;
    int len = end - beg;

    float4 acc = make_float4(0.f, 0.f, 0.f, 0.f);
    if (valid)
        acc = __ldg((const float4*)(g + (size_t)node * F) + sub);

    int maxlen = len;
#pragma unroll
    for (int off = 16; off; off >>= 1)
        maxlen = max(maxlen, __shfl_xor_sync(0xffffffffu, maxlen, off));

    int s_pre = 0;
    for (int t = 0; t < maxlen; t++) {
        if ((t % GROUP) == 0) {
            int j = beg + t + sub;
            s_pre = (j < end) ? __ldg(&d_csr[j]) : 0;
        }
        int ss = __shfl_sync(0xffffffffu, s_pre, base + (t % GROUP));
        if (t < len) {
            float4 v = __ldg((const float4*)(g + (size_t)ss * F) + sub);
            acc.x += v.x; acc.y += v.y; acc.z += v.z; acc.w += v.w;
        }
    }
    if (valid)
        *((float4*)(o + (size_t)node * F) + sub) = acc;
}

// ------- layer 3 GEMM: relu(dinv*o2+b2) @ W3, fused dinv ------
__global__ void __launch_bounds__(256) k_gemm3(const float* __restrict__ W3,
                                               const float* __restrict__ b2) {
    __shared__ float Ws[64 * 8];
    __shared__ float Bb[64];
    __shared__ __align__(16) float Hs[32][65];
    int tid = threadIdx.x;
    for (int i = tid; i < 512; i += 256) Ws[i] = W3[i];
    if (tid < 64) Bb[tid] = b2[tid];
    int nodeBase = blockIdx.x * 32;
    __syncthreads();
    for (int i = tid; i < 512; i += 256) {
        int r = i / 16, c4 = i % 16;
        int node = nodeBase + r;
        if (node < NNODES) {
            float dv = d_dinv[node];
            float4 v = *(const float4*)(d_o2 + (size_t)node * 64 + c4 * 4);
            Hs[r][c4 * 4 + 0] = fmaxf(fmaf(dv, v.x, Bb[c4 * 4 + 0]), 0.f);
            Hs[r][c4 * 4 + 1] = fmaxf(fmaf(dv, v.y, Bb[c4 * 4 + 1]), 0.f);
            Hs[r][c4 * 4 + 2] = fmaxf(fmaf(dv, v.z, Bb[c4 * 4 + 2]), 0.f);
            Hs[r][c4 * 4 + 3] = fmaxf(fmaf(dv, v.w, Bb[c4 * 4 + 3]), 0.f);
        }
    }
    __syncthreads();
    int ln = tid / 8, col = tid % 8;
    int node = nodeBase + ln;
    if (node >= NNODES) return;
    float acc = 0.f;
#pragma unroll
    for (int k = 0; k < 64; k++) acc = fmaf(Hs[ln][k], Ws[k * 8 + col], acc);
    d_g3[(size_t)node * 8 + col] = d_dinv[node] * acc;
}

// ---------------- final head ----------------
__global__ void k_head(const float* __restrict__ Wc, const float* __restrict__ bc,
                       const float* __restrict__ b3, float* __restrict__ out) {
    int n = blockIdx.x * blockDim.x + threadIdx.x;
    if (n >= NNODES) return;
    float dv = d_dinv[n];
    float4 p0 = *(const float4*)(d_o3 + (size_t)n * 8);
    float4 p1 = *(const float4*)(d_o3 + (size_t)n * 8 + 4);
    float h[8] = {p0.x, p0.y, p0.z, p0.w, p1.x, p1.y, p1.z, p1.w};
    float r0 = __ldg(&bc[0]), r1 = __ldg(&bc[1]), r2 = __ldg(&bc[2]);
#pragma unroll
    for (int j = 0; j < 8; j++) {
        float hv = fmaxf(fmaf(dv, h[j], __ldg(&b3[j])), 0.f);
        r0 = fmaf(hv, __ldg(&Wc[j * 3 + 0]), r0);
        r1 = fmaf(hv, __ldg(&Wc[j * 3 + 1]), r1);
        r2 = fmaf(hv, __ldg(&Wc[j * 3 + 2]), r2);
    }
    out[(size_t)n * 3 + 0] = r0;
    out[(size_t)n * 3 + 1] = r1;
    out[(size_t)n * 3 + 2] = r2;
}

// ---------------- launch ----------------
extern "C" void kernel_launch(void* const* d_in, const int* in_sizes, int n_in,
                              void* d_out, int out_size) {
    const float* latent = (const float*)d_in[0];
    const float* hist   = (const float*)d_in[1];
    const float* subg   = (const float*)d_in[2];
    const void*  ei     = d_in[3];
    const float* W1 = (const float*)d_in[4];
    const float* b1 = (const float*)d_in[5];
    const float* W2 = (const float*)d_in[6];
    const float* b2 = (const float*)d_in[7];
    const float* W3 = (const float*)d_in[8];
    const float* b3 = (const float*)d_in[9];
    const float* Wc = (const float*)d_in[10];
    const float* bc = (const float*)d_in[11];
    float* out = (float*)d_out;

    __half *g1h, *g2h;
    float *o1, *o2, *g3, *o3;
    cudaGetSymbolAddress((void**)&g1h, d_g1h);
    cudaGetSymbolAddress((void**)&o1, d_o1);
    cudaGetSymbolAddress((void**)&g2h, d_g2h);
    cudaGetSymbolAddress((void**)&o2, d_o2);
    cudaGetSymbolAddress((void**)&g3, d_g3);
    cudaGetSymbolAddress((void**)&o3, d_o3);

    k_detect<<<1, 32>>>((const int*)ei);
    k_deg_init<<<(NNODES + 255) / 256, 256>>>();
    k_edge_prep<<<(NEDGES + 255) / 256, 256>>>(ei);
    k_dinv<<<(NNODES + 255) / 256, 256>>>();
    k_wprep<<<(256 * 128 + 255) / 256, 256>>>(W1, W2);

    // GEMM1 on tensor cores (mma.sync bf16-split), fp16 output
    k_gemm1_mma<<<(NNODES + 127) / 128, 256>>>(latent, W1, hist, subg, g1h);

    // CSR build
    k_scan1<<<SCAN_NB, SCAN_BLK>>>();
    k_scan2<<<1, SCAN_BLK>>>();
    k_scan3<<<(NNODES + 255) / 256, 256>>>();
    k_csr_fill<<<(NEDGES + 255) / 256, 256>>>(ei);

    // layer 1 aggregate (fp16 source, fp32 accumulate)
    k_gather_h<128, 16><<<(NNODES * 16 + 255) / 256, 256>>>(g1h, o1);

    // layer 2 on tensor cores, fused relu(dinv*o1+b1), fp16 output
    k_gemm2_mma<<<(NNODES + 127) / 128, 256>>>(o1, b1, g2h);
    k_gather_h<64, 8><<<(NNODES * 8 + 255) / 256, 256>>>(g2h, o2);

    // layer 3: 64 -> 8
    k_gemm3<<<(NNODES + 31) / 32, 256>>>(W3, b2);
    k_gather<8, 2><<<(NNODES * 2 + 255) / 256, 256>>>(g3, o3);

    k_head<<<(NNODES + 255) / 256, 256>>>(Wc, bc, b3, out);
}

// round 10
// speedup vs baseline: 3.0461x; 1.2661x over previous
#include <cuda_runtime.h>
#include <cuda_fp16.h>
#include <math.h>
#include <stdint.h>

#define NNODES 200000
#define NEDGES 3200000
#define SCAN_BLK 512
#define SCAN_NB ((NNODES + SCAN_BLK - 1) / SCAN_BLK)   // 391

// ---------------- scratch (no allocations allowed) ----------------
__device__ __align__(256) int   d_degi[NNODES];
__device__ __align__(256) float d_dinv[NNODES];
__device__ __align__(256) int   d_csr[NEDGES];
__device__ __align__(256) int   d_rowptr[NNODES + 1];
__device__ __align__(256) int   d_cursor[NNODES];
__device__ __align__(256) int   d_bsum[SCAN_NB];
__device__ __align__(256) int   d_boff[SCAN_NB];
__device__ __align__(256) unsigned short d_w1hi[256 * 128];  // [k][n] fp16 hi
__device__ __align__(256) unsigned short d_w1lo[256 * 128];  // fp16 lo
__device__ __align__(256) unsigned short d_w2hi[128 * 64];
__device__ __align__(256) unsigned short d_w2lo[128 * 64];
__device__ __align__(256) __half d_g1h[(size_t)NNODES * 128];
__device__ __align__(256) __half d_o1h[(size_t)NNODES * 128];
__device__ __align__(256) __half d_g2h[(size_t)NNODES * 64];
__device__ __align__(256) __half d_o2h[(size_t)NNODES * 64];
__device__ __align__(256) float d_g3[(size_t)NNODES * 8];
__device__ __align__(256) float d_o3[(size_t)NNODES * 8];
__device__ int d_is64;

// ---------------- PTX helpers (baseline ISA, sm_103-safe) -------------
__device__ __forceinline__ uint32_t smem_u32(const void* p) {
    uint32_t a;
    asm("{ .reg .u64 t; cvta.to.shared.u64 t, %1; cvt.u32.u64 %0, t; }"
        : "=r"(a) : "l"(p));
    return a;
}
__device__ __forceinline__ void ldmx4(uint32_t* r, uint32_t addr) {
    asm volatile("ldmatrix.sync.aligned.m8n8.x4.shared.b16 {%0,%1,%2,%3}, [%4];"
                 : "=r"(r[0]), "=r"(r[1]), "=r"(r[2]), "=r"(r[3]) : "r"(addr));
}
__device__ __forceinline__ void ldmx4t(uint32_t* r, uint32_t addr) {
    asm volatile("ldmatrix.sync.aligned.m8n8.x4.trans.shared.b16 {%0,%1,%2,%3}, [%4];"
                 : "=r"(r[0]), "=r"(r[1]), "=r"(r[2]), "=r"(r[3]) : "r"(addr));
}
__device__ __forceinline__ void mma16816f(float* d, const uint32_t* a, const uint32_t* b) {
    asm volatile("mma.sync.aligned.m16n8k16.row.col.f32.f16.f16.f32 "
                 "{%0,%1,%2,%3}, {%4,%5,%6,%7}, {%8,%9}, {%0,%1,%2,%3};"
                 : "+f"(d[0]), "+f"(d[1]), "+f"(d[2]), "+f"(d[3])
                 : "r"(a[0]), "r"(a[1]), "r"(a[2]), "r"(a[3]),
                   "r"(b[0]), "r"(b[1]));
}
__device__ __forceinline__ void h_split(float x, unsigned short& hi, unsigned short& lo) {
    __half h = __float2half_rn(x);
    hi = __half_as_ushort(h);
    lo = __half_as_ushort(__float2half_rn(x - __half2float(h)));
}
__device__ __forceinline__ uint2 pack4h(float a, float b, float c, float d) {
    __half2 p0 = __floats2half2_rn(a, b);
    __half2 p1 = __floats2half2_rn(c, d);
    uint2 r;
    r.x = *(uint32_t*)&p0;
    r.y = *(uint32_t*)&p1;
    return r;
}

// ---------------- edge dtype detection ----------------
__global__ void k_detect(const int* __restrict__ ei32) {
    if (threadIdx.x == 0 && blockIdx.x == 0) {
        int zeros = 0;
#pragma unroll
        for (int i = 0; i < 64; i++)
            if (ei32[2 * i + 1] == 0) zeros++;
        d_is64 = (zeros >= 60) ? 1 : 0;
    }
}

__global__ void k_deg_init() {
    int i = blockIdx.x * blockDim.x + threadIdx.x;
    if (i < NNODES) d_degi[i] = 0;
}

__global__ void k_edge_prep(const void* __restrict__ ei) {   // degree over dst
    int e = blockIdx.x * blockDim.x + threadIdx.x;
    if (e >= NEDGES) return;
    int d = d_is64 ? (int)((const long long*)ei)[(size_t)NEDGES + e]
                   : ((const int*)ei)[NEDGES + e];
    atomicAdd(&d_degi[d], 1);
}

__global__ void k_dinv() {
    int i = blockIdx.x * blockDim.x + threadIdx.x;
    if (i < NNODES) d_dinv[i] = rsqrtf((float)(d_degi[i] + 1));
}

// ---------------- W1/W2 -> fp16 hi/lo planes, [k][n] layout ----------------
__global__ void k_wprep(const float* __restrict__ W1, const float* __restrict__ W2) {
    int idx = blockIdx.x * blockDim.x + threadIdx.x;
    if (idx < 256 * 128) {
        unsigned short hi, lo;
        h_split(W1[idx], hi, lo);
        d_w1hi[idx] = hi;
        d_w1lo[idx] = lo;
    }
    if (idx < 128 * 64) {
        unsigned short hi, lo;
        h_split(W2[idx], hi, lo);
        d_w2hi[idx] = hi;
        d_w2lo[idx] = lo;
    }
}

// ---------------- scan -> rowptr ----------------
__global__ void k_scan1() {
    __shared__ int sh[SCAN_BLK];
    int i = blockIdx.x * SCAN_BLK + threadIdx.x;
    int v = (i < NNODES) ? d_degi[i] : 0;
    sh[threadIdx.x] = v;
    __syncthreads();
    int incl = v;
#pragma unroll
    for (int off = 1; off < SCAN_BLK; off <<= 1) {
        int add = (threadIdx.x >= off) ? sh[threadIdx.x - off] : 0;
        __syncthreads();
        incl += add;
        sh[threadIdx.x] = incl;
        __syncthreads();
    }
    if (i < NNODES) d_rowptr[i] = incl - v;
    if (threadIdx.x == SCAN_BLK - 1) d_bsum[blockIdx.x] = incl;
}
__global__ void k_scan2() {
    __shared__ int sh[SCAN_BLK];
    int t = threadIdx.x;
    int v = (t < SCAN_NB) ? d_bsum[t] : 0;
    sh[t] = v;
    __syncthreads();
    int incl = v;
#pragma unroll
    for (int off = 1; off < SCAN_BLK; off <<= 1) {
        int add = (t >= off) ? sh[t - off] : 0;
        __syncthreads();
        incl += add;
        sh[t] = incl;
        __syncthreads();
    }
    if (t < SCAN_NB) d_boff[t] = incl - v;
}
__global__ void k_scan3() {
    int i = blockIdx.x * blockDim.x + threadIdx.x;
    if (i < NNODES) {
        int r = d_rowptr[i] + d_boff[i / SCAN_BLK];
        d_rowptr[i] = r;
        d_cursor[i] = r;
    }
    if (i == 0) d_rowptr[NNODES] = NEDGES;
}
__global__ void k_csr_fill(const void* __restrict__ ei) {
    int e = blockIdx.x * blockDim.x + threadIdx.x;
    if (e >= NEDGES) return;
    int s, d;
    if (d_is64) {
        const long long* p = (const long long*)ei;
        s = (int)p[e];
        d = (int)p[(size_t)NEDGES + e];
    } else {
        const int* p = (const int*)ei;
        s = p[e];
        d = p[NEDGES + e];
    }
    int pos = atomicAdd(&d_cursor[d], 1);
    d_csr[pos] = s;
}

// ========== GEMM1: fp16 2-MMA (A hi, W hi+lo), 128x128 tile, K=256 ==========
// g1h[row] = (fp16) dinv[row]*(latent@W1[0:256] + hist*W1[256] + subg*W1[257])
#define APAD 40
#define BPAD 136
__global__ void __launch_bounds__(256)
k_gemm1_mma(const float* __restrict__ A, const float* __restrict__ W1,
            const float* __restrict__ hist, const float* __restrict__ subg,
            __half* __restrict__ g) {
    __shared__ __align__(16) __half sA[128][APAD];
    __shared__ __align__(16) __half sBh[32][BPAD];
    __shared__ __align__(16) __half sBl[32][BPAD];

    const int tid = threadIdx.x;
    const int wid = tid >> 5, lane = tid & 31;
    const int rowBase = blockIdx.x * 128;
    const int mbase = (wid >> 1) * 32;
    const int nbase = (wid & 1) * 64;

    float acc[2][8][4];
#pragma unroll
    for (int i = 0; i < 2; i++)
#pragma unroll
        for (int j = 0; j < 8; j++)
#pragma unroll
            for (int q = 0; q < 4; q++) acc[i][j][q] = 0.f;

    const int aRow = lane & 15, aK = (lane >> 4) * 8;
    const int bK = lane & 15, bN = (lane >> 4) * 8;

    float4 va[4];
    uint4 vbh[2], vbl[2];

    auto loadA = [&](int k0) {
#pragma unroll
        for (int t = 0; t < 4; t++) {
            int idx = tid + t * 256;
            int m = idx >> 3, f4 = idx & 7;
            int row = rowBase + m;
            va[t] = make_float4(0.f, 0.f, 0.f, 0.f);
            if (row < NNODES)
                va[t] = *(const float4*)(A + (size_t)row * 256 + k0 + f4 * 4);
        }
    };
    auto loadB = [&](int k0) {
#pragma unroll
        for (int t = 0; t < 2; t++) {
            int idx = tid + t * 256;
            int k = idx >> 4, u = idx & 15;
            vbh[t] = *(const uint4*)(d_w1hi + (size_t)(k0 + k) * 128 + u * 8);
            vbl[t] = *(const uint4*)(d_w1lo + (size_t)(k0 + k) * 128 + u * 8);
        }
    };
    auto stage = [&]() {
#pragma unroll
        for (int t = 0; t < 4; t++) {
            int idx = tid + t * 256;
            int m = idx >> 3, f4 = idx & 7;
            *(uint2*)&sA[m][f4 * 4] = pack4h(va[t].x, va[t].y, va[t].z, va[t].w);
        }
#pragma unroll
        for (int t = 0; t < 2; t++) {
            int idx = tid + t * 256;
            int k = idx >> 4, u = idx & 15;
            *(uint4*)&sBh[k][u * 8] = vbh[t];
            *(uint4*)&sBl[k][u * 8] = vbl[t];
        }
    };

    loadA(0);
    loadB(0);
    for (int c = 0; c < 8; c++) {
        stage();
        __syncthreads();
        if (c < 7) { loadA((c + 1) * 32); loadB((c + 1) * 32); }
#pragma unroll
        for (int ks = 0; ks < 32; ks += 16) {
            uint32_t a[2][4], bh[4][4], bl[4][4];
#pragma unroll
            for (int mt = 0; mt < 2; mt++)
                ldmx4(a[mt], smem_u32(&sA[mbase + mt * 16 + aRow][ks + aK]));
#pragma unroll
            for (int ng = 0; ng < 4; ng++) {
                ldmx4t(bh[ng], smem_u32(&sBh[ks + bK][nbase + ng * 16 + bN]));
                ldmx4t(bl[ng], smem_u32(&sBl[ks + bK][nbase + ng * 16 + bN]));
            }
#pragma unroll
            for (int mt = 0; mt < 2; mt++)
#pragma unroll
                for (int ng = 0; ng < 4; ng++) {
                    mma16816f(acc[mt][ng * 2 + 0], a[mt], &bh[ng][0]);
                    mma16816f(acc[mt][ng * 2 + 0], a[mt], &bl[ng][0]);
                    mma16816f(acc[mt][ng * 2 + 1], a[mt], &bh[ng][2]);
                    mma16816f(acc[mt][ng * 2 + 1], a[mt], &bl[ng][2]);
                }
        }
        __syncthreads();
    }

#pragma unroll
    for (int mt = 0; mt < 2; mt++) {
        int r0 = rowBase + mbase + mt * 16 + (lane >> 2);
        int r1 = r0 + 8;
        float dv0 = 0.f, hv0 = 0.f, sv0 = 0.f, dv1 = 0.f, hv1 = 0.f, sv1 = 0.f;
        if (r0 < NNODES) { dv0 = d_dinv[r0]; hv0 = hist[r0]; sv0 = subg[r0]; }
        if (r1 < NNODES) { dv1 = d_dinv[r1]; hv1 = hist[r1]; sv1 = subg[r1]; }
#pragma unroll
        for (int nt = 0; nt < 8; nt++) {
            int col = nbase + nt * 8 + (lane & 3) * 2;
            float w2a = __ldg(&W1[(size_t)256 * 128 + col]);
            float w2b = __ldg(&W1[(size_t)256 * 128 + col + 1]);
            float w3a = __ldg(&W1[(size_t)257 * 128 + col]);
            float w3b = __ldg(&W1[(size_t)257 * 128 + col + 1]);
            if (r0 < NNODES) {
                float ox = (acc[mt][nt][0] + hv0 * w2a + sv0 * w3a) * dv0;
                float oy = (acc[mt][nt][1] + hv0 * w2b + sv0 * w3b) * dv0;
                *(__half2*)(g + (size_t)r0 * 128 + col) = __floats2half2_rn(ox, oy);
            }
            if (r1 < NNODES) {
                float ox = (acc[mt][nt][2] + hv1 * w2a + sv1 * w3a) * dv1;
                float oy = (acc[mt][nt][3] + hv1 * w2b + sv1 * w3b) * dv1;
                *(__half2*)(g + (size_t)r1 * 128 + col) = __floats2half2_rn(ox, oy);
            }
        }
    }
}

// -------- fp16 pull-gather -> fp16 out: F halves/row, GROUP=F/8 ------------
template<int F, int GROUP>
__global__ void k_gather_h(const __half* __restrict__ g, __half* __restrict__ o) {
    const int lane = threadIdx.x & 31;
    const int warp = (blockIdx.x * blockDim.x + threadIdx.x) >> 5;
    constexpr int NPW = 32 / GROUP;
    const int gid  = lane / GROUP;
    const int sub  = lane % GROUP;          // owns halves sub*8..sub*8+7
    const int base = gid * GROUP;
    const int node = warp * NPW + gid;
    const bool valid = node < NNODES;

    int beg = valid ? __ldg(&d_rowptr[node])     : 0;
    int end = valid ? __ldg(&d_rowptr[node + 1]) : 0;
    int len = end - beg;

    float acc[8];
#pragma unroll
    for (int j = 0; j < 8; j++) acc[j] = 0.f;

    auto addRow = [&](int ss) {
        uint4 q = __ldg((const uint4*)(g + (size_t)ss * F) + sub);
        float2 f0 = __half22float2(*(__half2*)&q.x);
        float2 f1 = __half22float2(*(__half2*)&q.y);
        float2 f2 = __half22float2(*(__half2*)&q.z);
        float2 f3 = __half22float2(*(__half2*)&q.w);
        acc[0] += f0.x; acc[1] += f0.y; acc[2] += f1.x; acc[3] += f1.y;
        acc[4] += f2.x; acc[5] += f2.y; acc[6] += f3.x; acc[7] += f3.y;
    };
    if (valid) addRow(node);             // self-loop

    int maxlen = len;
#pragma unroll
    for (int off = 16; off; off >>= 1)
        maxlen = max(maxlen, __shfl_xor_sync(0xffffffffu, maxlen, off));

    int s_pre = 0;
    for (int t = 0; t < maxlen; t++) {
        if ((t % GROUP) == 0) {
            int j = beg + t + sub;
            s_pre = (j < end) ? __ldg(&d_csr[j]) : 0;
        }
        int ss = __shfl_sync(0xffffffffu, s_pre, base + (t % GROUP));
        if (t < len) addRow(ss);
    }
    if (valid) {
        uint2 q0 = pack4h(acc[0], acc[1], acc[2], acc[3]);
        uint2 q1 = pack4h(acc[4], acc[5], acc[6], acc[7]);
        uint4 q;
        q.x = q0.x; q.y = q0.y; q.z = q1.x; q.w = q1.y;
        *((uint4*)(o + (size_t)node * F) + sub) = q;
    }
}

// ========== GEMM2: fp16 2-MMA, 128x64 tile, K=128, A from fp16 o1 ==========
// g2h[row] = (fp16) dinv[row] * (relu(dinv*o1+b1) @ W2)
#define BPAD2 72
__global__ void __launch_bounds__(256)
k_gemm2_mma(const __half* __restrict__ A, const float* __restrict__ b1,
            __half* __restrict__ g) {
    __shared__ __align__(16) __half sA[128][APAD];
    __shared__ __align__(16) __half sBh[32][BPAD2];
    __shared__ __align__(16) __half sBl[32][BPAD2];

    const int tid = threadIdx.x;
    const int wid = tid >> 5, lane = tid & 31;
    const int rowBase = blockIdx.x * 128;
    const int mbase = wid * 16;

    float acc[8][4];
#pragma unroll
    for (int j = 0; j < 8; j++)
#pragma unroll
        for (int q = 0; q < 4; q++) acc[j][q] = 0.f;

    const int aRow = lane & 15, aK = (lane >> 4) * 8;
    const int bK = lane & 15, bN = (lane >> 4) * 8;

    uint4 va[2];       // 8 halves each
    uint4 vbh, vbl;

    auto loadA = [&](int k0) {
#pragma unroll
        for (int t = 0; t < 2; t++) {
            int idx = tid + t * 256;       // 0..511
            int m = idx >> 2, f8 = idx & 3;
            int row = rowBase + m;
            va[t] = make_uint4(0, 0, 0, 0);
            if (row < NNODES)
                va[t] = *((const uint4*)(A + (size_t)row * 128) + (k0 >> 3) + f8);
        }
    };
    auto loadB = [&](int k0) {
        int k = tid >> 3, u = tid & 7;     // 256 uint4 per plane
        vbh = *(const uint4*)(d_w2hi + (size_t)(k0 + k) * 64 + u * 8);
        vbl = *(const uint4*)(d_w2lo + (size_t)(k0 + k) * 64 + u * 8);
    };
    auto stage = [&](int k0) {
#pragma unroll
        for (int t = 0; t < 2; t++) {
            int idx = tid + t * 256;
            int m = idx >> 2, f8 = idx & 3;
            int row = rowBase + m;
            float dv = (row < NNODES) ? d_dinv[row] : 0.f;
            int kk = k0 + f8 * 8;
            float2 f0 = __half22float2(*(__half2*)&va[t].x);
            float2 f1 = __half22float2(*(__half2*)&va[t].y);
            float2 f2 = __half22float2(*(__half2*)&va[t].z);
            float2 f3 = __half22float2(*(__half2*)&va[t].w);
            float r[8] = {f0.x, f0.y, f1.x, f1.y, f2.x, f2.y, f3.x, f3.y};
#pragma unroll
            for (int j = 0; j < 8; j++)
                r[j] = fmaxf(fmaf(dv, r[j], __ldg(&b1[kk + j])), 0.f);
            uint2 q0 = pack4h(r[0], r[1], r[2], r[3]);
            uint2 q1 = pack4h(r[4], r[5], r[6], r[7]);
            uint4 q;
            q.x = q0.x; q.y = q0.y; q.z = q1.x; q.w = q1.y;
            *(uint4*)&sA[m][f8 * 8] = q;
        }
        {
            int k = tid >> 3, u = tid & 7;
            *(uint4*)&sBh[k][u * 8] = vbh;
            *(uint4*)&sBl[k][u * 8] = vbl;
        }
    };

    loadA(0);
    loadB(0);
    for (int c = 0; c < 4; c++) {
        stage(c * 32);
        __syncthreads();
        if (c < 3) { loadA((c + 1) * 32); loadB((c + 1) * 32); }
#pragma unroll
        for (int ks = 0; ks < 32; ks += 16) {
            uint32_t a[4], bh[4][4], bl[4][4];
            ldmx4(a, smem_u32(&sA[mbase + aRow][ks + aK]));
#pragma unroll
            for (int ng = 0; ng < 4; ng++) {
                ldmx4t(bh[ng], smem_u32(&sBh[ks + bK][ng * 16 + bN]));
                ldmx4t(bl[ng], smem_u32(&sBl[ks + bK][ng * 16 + bN]));
            }
#pragma unroll
            for (int ng = 0; ng < 4; ng++) {
                mma16816f(acc[ng * 2 + 0], a, &bh[ng][0]);
                mma16816f(acc[ng * 2 + 0], a, &bl[ng][0]);
                mma16816f(acc[ng * 2 + 1], a, &bh[ng][2]);
                mma16816f(acc[ng * 2 + 1], a, &bl[ng][2]);
            }
        }
        __syncthreads();
    }

    int r0 = rowBase + mbase + (lane >> 2);
    int r1 = r0 + 8;
    float dv0 = (r0 < NNODES) ? d_dinv[r0] : 0.f;
    float dv1 = (r1 < NNODES) ? d_dinv[r1] : 0.f;
#pragma unroll
    for (int nt = 0; nt < 8; nt++) {
        int col = nt * 8 + (lane & 3) * 2;
        if (r0 < NNODES)
            *(__half2*)(g + (size_t)r0 * 64 + col) =
                __floats2half2_rn(acc[nt][0] * dv0, acc[nt][1] * dv0);
        if (r1 < NNODES)
            *(__half2*)(g + (size_t)r1 * 64 + col) =
                __floats2half2_rn(acc[nt][2] * dv1, acc[nt][3] * dv1);
    }
}

// ------------- CSR pull-gather (fp32, layer 3) ----------
template<int F, int GROUP>
__global__ void k_gather(const float* __restrict__ g, float* __restrict__ o) {
    const int lane = threadIdx.x & 31;
    const int warp = (blockIdx.x * blockDim.x + threadIdx.x) >> 5;
    constexpr int NPW = 32 / GROUP;
    const int gid  = lane / GROUP;
    const int sub  = lane % GROUP;
    const int base = gid * GROUP;
    const int node = warp * NPW + gid;
    const bool valid = node < NNODES;

    int beg = valid ? __ldg(&d_rowptr[node])     : 0;
    int end = valid ? __ldg(&d_rowptr[node + 1]) : 0;
    int len = end - beg;

    float4 acc = make_float4(0.f, 0.f, 0.f, 0.f);
    if (valid)
        acc = __ldg((const float4*)(g + (size_t)node * F) + sub);

    int maxlen = len;
#pragma unroll
    for (int off = 16; off; off >>= 1)
        maxlen = max(maxlen, __shfl_xor_sync(0xffffffffu, maxlen, off));

    int s_pre = 0;
    for (int t = 0; t < maxlen; t++) {
        if ((t % GROUP) == 0) {
            int j = beg + t + sub;
            s_pre = (j < end) ? __ldg(&d_csr[j]) : 0;
        }
        int ss = __shfl_sync(0xffffffffu, s_pre, base + (t % GROUP));
        if (t < len) {
            float4 v = __ldg((const float4*)(g + (size_t)ss * F) + sub);
            acc.x += v.x; acc.y += v.y; acc.z += v.z; acc.w += v.w;
        }
    }
    if (valid)
        *((float4*)(o + (size_t)node * F) + sub) = acc;
}

// ------- layer 3 GEMM: relu(dinv*o2+b2) @ W3, fused dinv, fp16 input ------
__global__ void __launch_bounds__(256) k_gemm3(const float* __restrict__ W3,
                                               const float* __restrict__ b2) {
    __shared__ float Ws[64 * 8];
    __shared__ float Bb[64];
    __shared__ __align__(16) float Hs[32][65];
    int tid = threadIdx.x;
    for (int i = tid; i < 512; i += 256) Ws[i] = W3[i];
    if (tid < 64) Bb[tid] = b2[tid];
    int nodeBase = blockIdx.x * 32;
    __syncthreads();
    {
        int r = tid >> 3, u = tid & 7;      // 32 rows x 8 uint4
        int node = nodeBase + r;
        if (node < NNODES) {
            float dv = d_dinv[node];
            uint4 q = *((const uint4*)(d_o2h + (size_t)node * 64) + u);
            float2 f0 = __half22float2(*(__half2*)&q.x);
            float2 f1 = __half22float2(*(__half2*)&q.y);
            float2 f2 = __half22float2(*(__half2*)&q.z);
            float2 f3 = __half22float2(*(__half2*)&q.w);
            float rr[8] = {f0.x, f0.y, f1.x, f1.y, f2.x, f2.y, f3.x, f3.y};
#pragma unroll
            for (int j = 0; j < 8; j++)
                Hs[r][u * 8 + j] = fmaxf(fmaf(dv, rr[j], Bb[u * 8 + j]), 0.f);
        } else {
#pragma unroll
            for (int j = 0; j < 8; j++) Hs[r][u * 8 + j] = 0.f;
        }
    }
    __syncthreads();
    int ln = tid / 8, col = tid % 8;
    int node = nodeBase + ln;
    if (node >= NNODES) return;
    float acc = 0.f;
#pragma unroll
    for (int k = 0; k < 64; k++) acc = fmaf(Hs[ln][k], Ws[k * 8 + col], acc);
    d_g3[(size_t)node * 8 + col] = d_dinv[node] * acc;
}

// ---------------- final head ----------------
__global__ void k_head(const float* __restrict__ Wc, const float* __restrict__ bc,
                       const float* __restrict__ b3, float* __restrict__ out) {
    int n = blockIdx.x * blockDim.x + threadIdx.x;
    if (n >= NNODES) return;
    float dv = d_dinv[n];
    float4 p0 = *(const float4*)(d_o3 + (size_t)n * 8);
    float4 p1 = *(const float4*)(d_o3 + (size_t)n * 8 + 4);
    float h[8] = {p0.x, p0.y, p0.z, p0.w, p1.x, p1.y, p1.z, p1.w};
    float r0 = __ldg(&bc[0]), r1 = __ldg(&bc[1]), r2 = __ldg(&bc[2]);
#pragma unroll
    for (int j = 0; j < 8; j++) {
        float hv = fmaxf(fmaf(dv, h[j], __ldg(&b3[j])), 0.f);
        r0 = fmaf(hv, __ldg(&Wc[j * 3 + 0]), r0);
        r1 = fmaf(hv, __ldg(&Wc[j * 3 + 1]), r1);
        r2 = fmaf(hv, __ldg(&Wc[j * 3 + 2]), r2);
    }
    out[(size_t)n * 3 + 0] = r0;
    out[(size_t)n * 3 + 1] = r1;
    out[(size_t)n * 3 + 2] = r2;
}

// ---------------- launch ----------------
extern "C" void kernel_launch(void* const* d_in, const int* in_sizes, int n_in,
                              void* d_out, int out_size) {
    const float* latent = (const float*)d_in[0];
    const float* hist   = (const float*)d_in[1];
    const float* subg   = (const float*)d_in[2];
    const void*  ei     = d_in[3];
    const float* W1 = (const float*)d_in[4];
    const float* b1 = (const float*)d_in[5];
    const float* W2 = (const float*)d_in[6];
    const float* b2 = (const float*)d_in[7];
    const float* W3 = (const float*)d_in[8];
    const float* b3 = (const float*)d_in[9];
    const float* Wc = (const float*)d_in[10];
    const float* bc = (const float*)d_in[11];
    float* out = (float*)d_out;

    __half *g1h, *o1h, *g2h, *o2h;
    float *g3, *o3;
    cudaGetSymbolAddress((void**)&g1h, d_g1h);
    cudaGetSymbolAddress((void**)&o1h, d_o1h);
    cudaGetSymbolAddress((void**)&g2h, d_g2h);
    cudaGetSymbolAddress((void**)&o2h, d_o2h);
    cudaGetSymbolAddress((void**)&g3, d_g3);
    cudaGetSymbolAddress((void**)&o3, d_o3);

    k_detect<<<1, 32>>>((const int*)ei);
    k_deg_init<<<(NNODES + 255) / 256, 256>>>();
    k_edge_prep<<<(NEDGES + 255) / 256, 256>>>(ei);
    k_dinv<<<(NNODES + 255) / 256, 256>>>();
    k_wprep<<<(256 * 128 + 255) / 256, 256>>>(W1, W2);

    // GEMM1 on tensor cores (fp16 2-MMA), fp16 output
    k_gemm1_mma<<<(NNODES + 127) / 128, 256>>>(latent, W1, hist, subg, g1h);

    // CSR build
    k_scan1<<<SCAN_NB, SCAN_BLK>>>();
    k_scan2<<<1, SCAN_BLK>>>();
    k_scan3<<<(NNODES + 255) / 256, 256>>>();
    k_csr_fill<<<(NEDGES + 255) / 256, 256>>>(ei);

    // layer 1 aggregate (fp16 in, fp16 out, fp32 accumulate)
    k_gather_h<128, 16><<<(NNODES * 16 + 255) / 256, 256>>>(g1h, o1h);

    // layer 2 on tensor cores, fused relu(dinv*o1+b1), fp16 in/out
    k_gemm2_mma<<<(NNODES + 127) / 128, 256>>>(o1h, b1, g2h);
    k_gather_h<64, 8><<<(NNODES * 8 + 255) / 256, 256>>>(g2h, o2h);

    // layer 3: 64 -> 8
    k_gemm3<<<(NNODES + 31) / 32, 256>>>(W3, b2);
    k_gather<8, 2><<<(NNODES * 2 + 255) / 256, 256>>>(g3, o3);

    k_head<<<(NNODES + 255) / 256, 256>>>(Wc, bc, b3, out);
}